// round 4
// baseline (speedup 1.0000x reference)
#include <cuda_runtime.h>
#include <cuda_bf16.h>
#include <math.h>

#define N_NODES 50000
#define N_EDGES 600000
#define DIM 128
#define NUM_CLASSES 10
#define EPSF 1e-15f
#define MAX_NORM (1.0f - 1e-5f)

#define BM 16                      // nodes per tile in transform kernel
#define TPITCH 20                  // padded row pitch (floats) for t2[k][r]; 80B (16B-aligned)
#define WPITCH 129                 // padded pitch for transposed W in smem

// smem layout (floats): Wsh[128*129] | t2[128*20] | red[64] | fac[16]
#define SM_W    0
#define SM_T2   (DIM * WPITCH)
#define SM_RED  (SM_T2 + DIM * TPITCH)
#define SM_FAC  (SM_RED + 64)
#define SMEM_FLOATS (SM_FAC + 16)
#define SMEM_BYTES (SMEM_FLOATS * 4)

#define SCAN_B 1024
#define SCAN_NB ((N_NODES + SCAN_B - 1) / SCAN_B)   // 49

typedef unsigned long long u64;

// scratch (device globals: no allocation allowed)
__device__ float g_y[N_NODES * DIM];
__device__ float g_agg[N_NODES * DIM];
__device__ int   g_mult;                 // 1 if edge_index int32, 2 if int64 (stride in i32 words)
__device__ int   g_count[N_NODES];       // histogram
__device__ int   g_cursor[N_NODES];      // bucket cursors
__device__ int   g_rowstart[N_NODES + 1];
__device__ int   g_bsum[SCAN_NB];
__device__ int   g_boff[SCAN_NB];
__device__ int   g_esrc[N_EDGES];        // CSR: src node per slot, grouped by dst

// ---------------------------------------------------------------------------
// packed fp32x2 helpers (Blackwell dual-rate FFMA2 — PTX-only)
__device__ __forceinline__ u64 fma2(u64 a, u64 b, u64 c) {
    u64 d;
    asm("fma.rn.f32x2 %0, %1, %2, %3;" : "=l"(d) : "l"(a), "l"(b), "l"(c));
    return d;
}
__device__ __forceinline__ u64 pack2(float lo, float hi) {
    u64 r;
    asm("mov.b64 %0, {%1, %2};" : "=l"(r) : "f"(lo), "f"(hi));
    return r;
}
__device__ __forceinline__ void unpack2(u64 v, float& lo, float& hi) {
    asm("mov.b64 {%0, %1}, %2;" : "=f"(lo), "=f"(hi) : "l"(v));
}

// ---------------------------------------------------------------------------
// zero histogram + (block 0) detect edge dtype.
// int64 edge values < 50000 have zero high words at odd int32 slots; random
// int32 indices make 64 consecutive odd slots all-zero impossible.
__global__ void zero_detect_kernel(int* __restrict__ p, int n,
                                   const int* __restrict__ e32) {
    if (blockIdx.x == 0 && threadIdx.x < 64) {
        __shared__ int bad;
        if (threadIdx.x == 0) bad = 0;
        __syncwarp();
        int v1 = e32[2 * threadIdx.x + 1];
        if (__any_sync(0xffffffffu, v1 != 0)) bad = 1;
        __syncwarp();
        if (threadIdx.x == 0) g_mult = bad ? 1 : 2;
    }
    int i = blockIdx.x * blockDim.x + threadIdx.x;
    int stride = gridDim.x * blockDim.x;
    for (; i < n; i += stride) p[i] = 0;
}

__global__ void hist_kernel(const int* __restrict__ e32, int* __restrict__ cnt) {
    int e = blockIdx.x * blockDim.x + threadIdx.x;
    if (e >= N_EDGES) return;
    int m = g_mult;
    int dst = e32[(long long)(N_EDGES + e) * m];
    atomicAdd(&cnt[dst], 1);
}

// exclusive scan phase 1: per-block scan of 1024 elements
__global__ void scan1_kernel(const int* __restrict__ cnt, int* __restrict__ rs,
                             int* __restrict__ bsum) {
    __shared__ int wsum[32];
    const int b = blockIdx.x, t = threadIdx.x;
    const int i = b * SCAN_B + t;
    const int lane = t & 31, w = t >> 5;
    int v = (i < N_NODES) ? cnt[i] : 0;
    int x = v;
#pragma unroll
    for (int d = 1; d < 32; d <<= 1) {
        int y = __shfl_up_sync(0xffffffffu, x, d);
        if (lane >= d) x += y;
    }
    if (lane == 31) wsum[w] = x;
    __syncthreads();
    if (w == 0) {
        int s = wsum[lane];
#pragma unroll
        for (int d = 1; d < 32; d <<= 1) {
            int y = __shfl_up_sync(0xffffffffu, s, d);
            if (lane >= d) s += y;
        }
        wsum[lane] = s;
    }
    __syncthreads();
    int excl = x - v + (w ? wsum[w - 1] : 0);
    if (i < N_NODES) rs[i] = excl;
    if (t == SCAN_B - 1) bsum[b] = excl + v;
}

// phase 2: scan the 49 block totals (single block, 64 threads)
__global__ void scan2_kernel(const int* __restrict__ bsum, int* __restrict__ boff) {
    __shared__ int w0tot;
    const int t = threadIdx.x;
    const int lane = t & 31, w = t >> 5;
    int v = (t < SCAN_NB) ? bsum[t] : 0;
    int x = v;
#pragma unroll
    for (int d = 1; d < 32; d <<= 1) {
        int y = __shfl_up_sync(0xffffffffu, x, d);
        if (lane >= d) x += y;
    }
    if (w == 0 && lane == 31) w0tot = x;
    __syncthreads();
    int excl = x - v + (w ? w0tot : 0);
    if (t < SCAN_NB) boff[t] = excl;
}

// phase 3: add block offsets, init cursors, cap rowstart
__global__ void scan3_kernel(int* __restrict__ rs, const int* __restrict__ boff,
                             int* __restrict__ cursor) {
    int i = blockIdx.x * SCAN_B + threadIdx.x;
    if (i < N_NODES) {
        int v = rs[i] + boff[blockIdx.x];
        rs[i] = v;
        cursor[i] = v;
    }
    if (i == 0) rs[N_NODES] = N_EDGES;
}

// bucket scatter: place src ids grouped by dst
__global__ void build_kernel(const int* __restrict__ e32, int* __restrict__ cursor,
                             int* __restrict__ esrc) {
    int e = blockIdx.x * blockDim.x + threadIdx.x;
    if (e >= N_EDGES) return;
    int m = g_mult;
    int src = e32[(long long)e * m];
    int dst = e32[(long long)(N_EDGES + e) * m];
    int pos = atomicAdd(&cursor[dst], 1);
    esrc[pos] = src;
}

// ---------------------------------------------------------------------------
// Warp-level CSR row gather with 4-deep MLP. Returns per-lane float4 sum.
__device__ __forceinline__ float4 gather_row(const int* __restrict__ esrc,
                                             const float* __restrict__ y,
                                             int s, int e, int lane4) {
    float4 a0 = make_float4(0.f, 0.f, 0.f, 0.f);
    float4 a1 = make_float4(0.f, 0.f, 0.f, 0.f);
    float4 a2 = make_float4(0.f, 0.f, 0.f, 0.f);
    float4 a3 = make_float4(0.f, 0.f, 0.f, 0.f);
    int i = s;
    for (; i + 4 <= e; i += 4) {
        int s0 = __ldg(&esrc[i + 0]);
        int s1 = __ldg(&esrc[i + 1]);
        int s2 = __ldg(&esrc[i + 2]);
        int s3 = __ldg(&esrc[i + 3]);
        float4 v0 = __ldg((const float4*)&y[s0 * DIM + lane4]);
        float4 v1 = __ldg((const float4*)&y[s1 * DIM + lane4]);
        float4 v2 = __ldg((const float4*)&y[s2 * DIM + lane4]);
        float4 v3 = __ldg((const float4*)&y[s3 * DIM + lane4]);
        a0.x += v0.x; a0.y += v0.y; a0.z += v0.z; a0.w += v0.w;
        a1.x += v1.x; a1.y += v1.y; a1.z += v1.z; a1.w += v1.w;
        a2.x += v2.x; a2.y += v2.y; a2.z += v2.z; a2.w += v2.w;
        a3.x += v3.x; a3.y += v3.y; a3.z += v3.z; a3.w += v3.w;
    }
    if (i + 2 <= e) {
        int s0 = __ldg(&esrc[i + 0]);
        int s1 = __ldg(&esrc[i + 1]);
        float4 v0 = __ldg((const float4*)&y[s0 * DIM + lane4]);
        float4 v1 = __ldg((const float4*)&y[s1 * DIM + lane4]);
        a0.x += v0.x; a0.y += v0.y; a0.z += v0.z; a0.w += v0.w;
        a1.x += v1.x; a1.y += v1.y; a1.z += v1.z; a1.w += v1.w;
        i += 2;
    }
    if (i < e) {
        int s0 = __ldg(&esrc[i]);
        float4 v0 = __ldg((const float4*)&y[s0 * DIM + lane4]);
        a2.x += v0.x; a2.y += v0.y; a2.z += v0.z; a2.w += v0.w;
    }
    float4 r;
    r.x = (a0.x + a1.x) + (a2.x + a3.x);
    r.y = (a0.y + a1.y) + (a2.y + a3.y);
    r.z = (a0.z + a1.z) + (a2.z + a3.z);
    r.w = (a0.w + a1.w) + (a2.w + a3.w);
    return r;
}

// Aggregation layer 1: one warp per dst node, register accumulation, no atomics.
__global__ void __launch_bounds__(256)
gather_kernel(const int* __restrict__ esrc, const int* __restrict__ rs,
              const float* __restrict__ y, float* __restrict__ agg) {
    const int lane = threadIdx.x & 31;
    const int wid  = threadIdx.x >> 5;
    const int node = blockIdx.x * (blockDim.x >> 5) + wid;
    if (node >= N_NODES) return;
    const int s = rs[node];
    const int e = rs[node + 1];
    float4 r = gather_row(esrc, y, s, e, lane * 4);
    *(float4*)&agg[node * DIM + lane * 4] = r;
}

// Aggregation layer 2 fused with classifier: gather -> relu -> logmap0 -> Wc
__global__ void __launch_bounds__(256)
gather_cls_kernel(const int* __restrict__ esrc, const int* __restrict__ rs,
                  const float* __restrict__ y, const float* __restrict__ Wc,
                  const float* __restrict__ bc, float* __restrict__ out) {
    __shared__ float Wcs[NUM_CLASSES * DIM];
    __shared__ float bcs[NUM_CLASSES];
    const int tid = threadIdx.x;
    for (int i = tid; i < NUM_CLASSES * DIM; i += blockDim.x) Wcs[i] = Wc[i];
    if (tid < NUM_CLASSES) bcs[tid] = bc[tid];
    __syncthreads();

    const int lane = tid & 31;
    const int wid  = tid >> 5;
    const int node = blockIdx.x * (blockDim.x >> 5) + wid;
    if (node >= N_NODES) return;

    const int s = rs[node];
    const int e = rs[node + 1];
    float4 h = gather_row(esrc, y, s, e, lane * 4);

    h.x = fmaxf(h.x, 0.f); h.y = fmaxf(h.y, 0.f);
    h.z = fmaxf(h.z, 0.f); h.w = fmaxf(h.w, 0.f);

    float sq = h.x * h.x + h.y * h.y + h.z * h.z + h.w * h.w;
    sq += __shfl_xor_sync(0xffffffff, sq, 16);
    sq += __shfl_xor_sync(0xffffffff, sq, 8);
    sq += __shfl_xor_sync(0xffffffff, sq, 4);
    sq += __shfl_xor_sync(0xffffffff, sq, 2);
    sq += __shfl_xor_sync(0xffffffff, sq, 1);
    float n = fmaxf(sqrtf(sq), EPSF);
    float f = atanhf(fminf(n, MAX_NORM)) / n;
    float4 t = make_float4(f * h.x, f * h.y, f * h.z, f * h.w);

#pragma unroll
    for (int c = 0; c < NUM_CLASSES; c++) {
        float4 w = *(const float4*)&Wcs[c * DIM + lane * 4];
        float p = t.x * w.x + t.y * w.y + t.z * w.z + t.w * w.w;
        p += __shfl_xor_sync(0xffffffff, p, 16);
        p += __shfl_xor_sync(0xffffffff, p, 8);
        p += __shfl_xor_sync(0xffffffff, p, 4);
        p += __shfl_xor_sync(0xffffffff, p, 2);
        p += __shfl_xor_sync(0xffffffff, p, 1);
        if (lane == 0) out[node * NUM_CLASSES + c] = p + bcs[c];
    }
}

// ---------------------------------------------------------------------------
// Fused: (optional relu) -> logmap0 -> h = t @ W^T + b -> expmap0
// 128 threads, BM=16 nodes/tile, persistent; packed f32x2 FMA inner loop.
__global__ void __launch_bounds__(128, 2)
transform_kernel(const float* __restrict__ in, const float* __restrict__ W,
                 const float* __restrict__ bias, float* __restrict__ out,
                 int do_relu) {
    extern __shared__ float sm[];
    float* Wsh = sm + SM_W;
    float* t2  = sm + SM_T2;
    float* red = sm + SM_RED;
    float* fac = sm + SM_FAC;

    const int tid  = threadIdx.x;
    const int lane = tid & 31;
    const int wid  = tid >> 5;

    // Load W transposed into smem: Wsh[k*129 + j] = W[j*128 + k]
    for (int idx = tid; idx < DIM * DIM; idx += 128) {
        int j = idx >> 7, k = idx & 127;
        Wsh[k * WPITCH + j] = W[idx];
    }
    const float bj = bias[tid];
    __syncthreads();

    const int ntiles = N_NODES / BM;   // 3125, exact
    for (int tile = blockIdx.x; tile < ntiles; tile += gridDim.x) {
        const int node0 = tile * BM;

        // ---- load inputs (thread tid owns column tid of all BM rows) ----
        float xv[BM];
#pragma unroll
        for (int r = 0; r < BM; r++) {
            float v = in[(node0 + r) * DIM + tid];
            if (do_relu) v = fmaxf(v, 0.f);
            xv[r] = v;
        }

        // ---- per-row sum of squares, reduced across 128 threads ----
        float ss[BM];
#pragma unroll
        for (int r = 0; r < BM; r++) {
            float s = xv[r] * xv[r];
            s += __shfl_xor_sync(0xffffffff, s, 16);
            s += __shfl_xor_sync(0xffffffff, s, 8);
            s += __shfl_xor_sync(0xffffffff, s, 4);
            s += __shfl_xor_sync(0xffffffff, s, 2);
            s += __shfl_xor_sync(0xffffffff, s, 1);
            ss[r] = s;
        }
        if (lane == 0) {
#pragma unroll
            for (int r = 0; r < BM; r++) red[wid * BM + r] = ss[r];
        }
        __syncthreads();
        if (tid < BM) {
            float s = red[0 * BM + tid] + red[1 * BM + tid] +
                      red[2 * BM + tid] + red[3 * BM + tid];
            float n = fmaxf(sqrtf(s), EPSF);
            fac[tid] = atanhf(fminf(n, MAX_NORM)) / n;   // logmap0 factor
        }
        __syncthreads();

        // ---- write t transposed: t2[k=tid][r], float4-packed ----
#pragma unroll
        for (int q = 0; q < 4; q++) {
            float4 tv;
            tv.x = xv[4 * q + 0] * fac[4 * q + 0];
            tv.y = xv[4 * q + 1] * fac[4 * q + 1];
            tv.z = xv[4 * q + 2] * fac[4 * q + 2];
            tv.w = xv[4 * q + 3] * fac[4 * q + 3];
            *(float4*)&t2[tid * TPITCH + 4 * q] = tv;
        }
        __syncthreads();

        // ---- GEMM inner loop (packed f32x2): thread tid = output column tid
        u64 acc2[8];
#pragma unroll
        for (int j = 0; j < 8; j++) acc2[j] = 0ULL;

#pragma unroll 4
        for (int k = 0; k < DIM; k++) {
            float w = Wsh[k * WPITCH + tid];
            u64 ww = pack2(w, w);
            const float* trow = &t2[k * TPITCH];
            ulonglong2 p0 = *(const ulonglong2*)(trow + 0);
            ulonglong2 p1 = *(const ulonglong2*)(trow + 4);
            ulonglong2 p2 = *(const ulonglong2*)(trow + 8);
            ulonglong2 p3 = *(const ulonglong2*)(trow + 12);
            acc2[0] = fma2(ww, p0.x, acc2[0]);
            acc2[1] = fma2(ww, p0.y, acc2[1]);
            acc2[2] = fma2(ww, p1.x, acc2[2]);
            acc2[3] = fma2(ww, p1.y, acc2[3]);
            acc2[4] = fma2(ww, p2.x, acc2[4]);
            acc2[5] = fma2(ww, p2.y, acc2[5]);
            acc2[6] = fma2(ww, p3.x, acc2[6]);
            acc2[7] = fma2(ww, p3.y, acc2[7]);
        }

        // ---- epilogue: + bias, expmap0 ----
        float hv[BM];
#pragma unroll
        for (int j = 0; j < 8; j++) {
            float lo, hi;
            unpack2(acc2[j], lo, hi);
            hv[2 * j + 0] = lo + bj;
            hv[2 * j + 1] = hi + bj;
        }

#pragma unroll
        for (int r = 0; r < BM; r++) {
            float s = hv[r] * hv[r];
            s += __shfl_xor_sync(0xffffffff, s, 16);
            s += __shfl_xor_sync(0xffffffff, s, 8);
            s += __shfl_xor_sync(0xffffffff, s, 4);
            s += __shfl_xor_sync(0xffffffff, s, 2);
            s += __shfl_xor_sync(0xffffffff, s, 1);
            ss[r] = s;
        }
        __syncthreads();   // protect red[] against stragglers of prior phase
        if (lane == 0) {
#pragma unroll
            for (int r = 0; r < BM; r++) red[wid * BM + r] = ss[r];
        }
        __syncthreads();
        if (tid < BM) {
            float s = red[0 * BM + tid] + red[1 * BM + tid] +
                      red[2 * BM + tid] + red[3 * BM + tid];
            float n = fmaxf(sqrtf(s), EPSF);
            fac[tid] = tanhf(n) / n;                     // expmap0 factor
        }
        __syncthreads();

#pragma unroll
        for (int r = 0; r < BM; r++)
            out[(node0 + r) * DIM + tid] = fac[r] * hv[r];
        __syncthreads();   // fac/red reused next tile
    }
}

// ---------------------------------------------------------------------------
extern "C" void kernel_launch(void* const* d_in, const int* in_sizes, int n_in,
                              void* d_out, int out_size) {
    const int*   e32 = (const int*)d_in[0];
    const float* x   = (const float*)d_in[1];
    const float* W1  = (const float*)d_in[2];
    const float* b1  = (const float*)d_in[3];
    const float* W2  = (const float*)d_in[4];
    const float* b2  = (const float*)d_in[5];
    const float* Wc  = (const float*)d_in[6];
    const float* bc  = (const float*)d_in[7];
    float* out = (float*)d_out;

    float *y, *agg;
    int *cnt, *cur, *rs, *bs, *bo, *es;
    cudaGetSymbolAddress((void**)&y,   g_y);
    cudaGetSymbolAddress((void**)&agg, g_agg);
    cudaGetSymbolAddress((void**)&cnt, g_count);
    cudaGetSymbolAddress((void**)&cur, g_cursor);
    cudaGetSymbolAddress((void**)&rs,  g_rowstart);
    cudaGetSymbolAddress((void**)&bs,  g_bsum);
    cudaGetSymbolAddress((void**)&bo,  g_boff);
    cudaGetSymbolAddress((void**)&es,  g_esrc);

    cudaFuncSetAttribute(transform_kernel,
                         cudaFuncAttributeMaxDynamicSharedMemorySize, SMEM_BYTES);

    const int eblocks = (N_EDGES + 255) / 256;
    const int gblocks = (N_NODES + 7) / 8;     // 8 warps/block

    // CSR build (once; edges identical for both layers)
    zero_detect_kernel<<<196, 256>>>(cnt, N_NODES, e32);
    hist_kernel<<<eblocks, 256>>>(e32, cnt);
    scan1_kernel<<<SCAN_NB, SCAN_B>>>(cnt, rs, bs);
    scan2_kernel<<<1, 64>>>(bs, bo);
    scan3_kernel<<<SCAN_NB, SCAN_B>>>(rs, bo, cur);
    build_kernel<<<eblocks, 256>>>(e32, cur, es);

    // layer 1
    transform_kernel<<<296, 128, SMEM_BYTES>>>(x, W1, b1, y, 0);
    gather_kernel<<<gblocks, 256>>>(es, rs, y, agg);
    // layer 2
    transform_kernel<<<296, 128, SMEM_BYTES>>>(agg, W2, b2, y, 1);
    // layer-2 aggregation fused with classifier
    gather_cls_kernel<<<gblocks, 256>>>(es, rs, y, Wc, bc, out);
}

// round 5
// speedup vs baseline: 1.0160x; 1.0160x over previous
#include <cuda_runtime.h>
#include <cuda_bf16.h>
#include <math.h>

#define N_NODES 50000
#define N_EDGES 600000
#define DIM 128
#define NUM_CLASSES 10
#define EPSF 1e-15f
#define MAX_NORM (1.0f - 1e-5f)

#define BM 16                      // nodes per tile in transform kernel
#define TPITCH 16                  // row pitch (floats) for t2[k][r]
#define WPITCH 129                 // padded pitch for transposed W in smem

// smem layout (floats): Wsh[128*129] | t2[128*16] | red[64] | fac[16]
#define SM_W    0
#define SM_T2   (DIM * WPITCH)
#define SM_RED  (SM_T2 + DIM * TPITCH)
#define SM_FAC  (SM_RED + 64)
#define SMEM_FLOATS (SM_FAC + 16)
#define SMEM_BYTES (SMEM_FLOATS * 4)

#define CSR_BLOCKS 49
#define CSR_THREADS 1024

typedef unsigned long long u64;

// scratch (device globals: no allocation allowed)
__device__ float g_y[N_NODES * DIM];
__device__ float g_agg[N_NODES * DIM];
__device__ int   g_mult;                 // 1 if edge_index int32, 2 if int64
__device__ int   g_count[N_NODES];       // histogram
__device__ int   g_cursor[N_NODES];      // bucket cursors
__device__ int   g_rowstart[N_NODES + 1];
__device__ int   g_bsum[CSR_BLOCKS];
// grid barrier state: gen is monotonic across graph replays, cnt self-resets.
__device__ volatile unsigned g_bar_gen;
__device__ unsigned g_bar_cnt;
__device__ int   g_esrc[N_EDGES];        // CSR: src node per slot, grouped by dst

// ---------------------------------------------------------------------------
// packed fp32x2 helpers (Blackwell dual-rate FFMA2 — PTX-only)
__device__ __forceinline__ u64 fma2(u64 a, u64 b, u64 c) {
    u64 d;
    asm("fma.rn.f32x2 %0, %1, %2, %3;" : "=l"(d) : "l"(a), "l"(b), "l"(c));
    return d;
}
__device__ __forceinline__ u64 pack2(float lo, float hi) {
    u64 r;
    asm("mov.b64 %0, {%1, %2};" : "=l"(r) : "f"(lo), "f"(hi));
    return r;
}
__device__ __forceinline__ void unpack2(u64 v, float& lo, float& hi) {
    asm("mov.b64 {%0, %1}, %2;" : "=f"(lo), "=f"(hi) : "l"(v));
}

// ---------------------------------------------------------------------------
// software grid barrier (all CSR_BLOCKS resident: 49 << 148 SMs)
__device__ __forceinline__ void grid_barrier() {
    __syncthreads();
    if (threadIdx.x == 0) {
        __threadfence();
        unsigned my = g_bar_gen;               // snapshot BEFORE arrive
        unsigned a = atomicAdd(&g_bar_cnt, 1);
        if (a == CSR_BLOCKS - 1) {
            g_bar_cnt = 0;                     // all arrived; safe to reset
            __threadfence();
            g_bar_gen = my + 1;                // release
        } else {
            while (g_bar_gen == my) __nanosleep(32);
        }
    }
    __syncthreads();
}

// ---------------------------------------------------------------------------
// Fused CSR build: detect dtype + zero hist + hist + scan + bucket scatter.
// One launch instead of six.
__global__ void __launch_bounds__(CSR_THREADS)
csr_kernel(const int* __restrict__ e32) {
    const int b = blockIdx.x, t = threadIdx.x;
    const int gid = b * CSR_THREADS + t;
    const int nth = CSR_BLOCKS * CSR_THREADS;   // 50176

    // ---- phase 0: dtype detect (warp 0 of block 0) + zero histogram ----
    // int64 values < 50000 have zero high words at odd int32 slots; 32
    // consecutive random int32 edge values being all zero is impossible.
    if (b == 0 && t < 32) {
        int v1 = e32[2 * t + 1];
        int bad = __any_sync(0xffffffffu, v1 != 0);
        if (t == 0) g_mult = bad ? 1 : 2;
    }
    if (gid < N_NODES) g_count[gid] = 0;
    grid_barrier();

    // ---- phase 1: histogram of dst ----
    const int m = g_mult;
    for (int e = gid; e < N_EDGES; e += nth) {
        int dst = e32[(long long)(N_EDGES + e) * m];
        atomicAdd(&g_count[dst], 1);
    }
    grid_barrier();

    // ---- phase 2a: per-block exclusive scan of 1024 counts ----
    __shared__ int wsum[32];
    __shared__ int part[2];
    const int lane = t & 31, w = t >> 5;
    int v = (gid < N_NODES) ? g_count[gid] : 0;
    int x = v;
#pragma unroll
    for (int d = 1; d < 32; d <<= 1) {
        int y = __shfl_up_sync(0xffffffffu, x, d);
        if (lane >= d) x += y;
    }
    if (lane == 31) wsum[w] = x;
    __syncthreads();
    if (w == 0) {
        int s = wsum[lane];
#pragma unroll
        for (int d = 1; d < 32; d <<= 1) {
            int y = __shfl_up_sync(0xffffffffu, s, d);
            if (lane >= d) s += y;
        }
        wsum[lane] = s;
    }
    __syncthreads();
    int excl = x - v + (w ? wsum[w - 1] : 0);
    if (t == CSR_THREADS - 1) g_bsum[b] = excl + v;
    grid_barrier();

    // ---- phase 2b: each block sums bsum[0..b-1] (two warps) ----
    if (t < 64) {
        int pv = (t < b) ? g_bsum[t] : 0;     // b <= 48 < 64
#pragma unroll
        for (int d = 16; d > 0; d >>= 1)
            pv += __shfl_xor_sync(0xffffffffu, pv, d);
        if (lane == 0) part[w] = pv;
    }
    __syncthreads();
    const int boff = part[0] + part[1];
    if (gid < N_NODES) {
        int rv = excl + boff;
        g_rowstart[gid] = rv;
        g_cursor[gid] = rv;
    }
    if (gid == 0) g_rowstart[N_NODES] = N_EDGES;
    grid_barrier();

    // ---- phase 3: bucket scatter of src grouped by dst ----
    for (int e = gid; e < N_EDGES; e += nth) {
        int src = e32[(long long)e * m];
        int dst = e32[(long long)(N_EDGES + e) * m];
        int pos = atomicAdd(&g_cursor[dst], 1);
        g_esrc[pos] = src;
    }
}

// ---------------------------------------------------------------------------
// Warp-level CSR row gather with 4-deep MLP. Returns per-lane float4 sum.
__device__ __forceinline__ float4 gather_row(const int* __restrict__ esrc,
                                             const float* __restrict__ y,
                                             int s, int e, int lane4) {
    float4 a0 = make_float4(0.f, 0.f, 0.f, 0.f);
    float4 a1 = make_float4(0.f, 0.f, 0.f, 0.f);
    float4 a2 = make_float4(0.f, 0.f, 0.f, 0.f);
    float4 a3 = make_float4(0.f, 0.f, 0.f, 0.f);
    int i = s;
    for (; i + 4 <= e; i += 4) {
        int s0 = __ldg(&esrc[i + 0]);
        int s1 = __ldg(&esrc[i + 1]);
        int s2 = __ldg(&esrc[i + 2]);
        int s3 = __ldg(&esrc[i + 3]);
        float4 v0 = __ldg((const float4*)&y[s0 * DIM + lane4]);
        float4 v1 = __ldg((const float4*)&y[s1 * DIM + lane4]);
        float4 v2 = __ldg((const float4*)&y[s2 * DIM + lane4]);
        float4 v3 = __ldg((const float4*)&y[s3 * DIM + lane4]);
        a0.x += v0.x; a0.y += v0.y; a0.z += v0.z; a0.w += v0.w;
        a1.x += v1.x; a1.y += v1.y; a1.z += v1.z; a1.w += v1.w;
        a2.x += v2.x; a2.y += v2.y; a2.z += v2.z; a2.w += v2.w;
        a3.x += v3.x; a3.y += v3.y; a3.z += v3.z; a3.w += v3.w;
    }
    if (i + 2 <= e) {
        int s0 = __ldg(&esrc[i + 0]);
        int s1 = __ldg(&esrc[i + 1]);
        float4 v0 = __ldg((const float4*)&y[s0 * DIM + lane4]);
        float4 v1 = __ldg((const float4*)&y[s1 * DIM + lane4]);
        a0.x += v0.x; a0.y += v0.y; a0.z += v0.z; a0.w += v0.w;
        a1.x += v1.x; a1.y += v1.y; a1.z += v1.z; a1.w += v1.w;
        i += 2;
    }
    if (i < e) {
        int s0 = __ldg(&esrc[i]);
        float4 v0 = __ldg((const float4*)&y[s0 * DIM + lane4]);
        a2.x += v0.x; a2.y += v0.y; a2.z += v0.z; a2.w += v0.w;
    }
    float4 r;
    r.x = (a0.x + a1.x) + (a2.x + a3.x);
    r.y = (a0.y + a1.y) + (a2.y + a3.y);
    r.z = (a0.z + a1.z) + (a2.z + a3.z);
    r.w = (a0.w + a1.w) + (a2.w + a3.w);
    return r;
}

// Aggregation layer 1: one warp per dst node, register accumulation, no atomics.
__global__ void __launch_bounds__(256)
gather_kernel(const int* __restrict__ esrc, const int* __restrict__ rs,
              const float* __restrict__ y, float* __restrict__ agg) {
    const int lane = threadIdx.x & 31;
    const int wid  = threadIdx.x >> 5;
    const int node = blockIdx.x * (blockDim.x >> 5) + wid;
    if (node >= N_NODES) return;
    const int s = rs[node];
    const int e = rs[node + 1];
    float4 r = gather_row(esrc, y, s, e, lane * 4);
    *(float4*)&agg[node * DIM + lane * 4] = r;
}

// Aggregation layer 2 fused with classifier: gather -> relu -> logmap0 -> Wc
__global__ void __launch_bounds__(256)
gather_cls_kernel(const int* __restrict__ esrc, const int* __restrict__ rs,
                  const float* __restrict__ y, const float* __restrict__ Wc,
                  const float* __restrict__ bc, float* __restrict__ out) {
    __shared__ float Wcs[NUM_CLASSES * DIM];
    __shared__ float bcs[NUM_CLASSES];
    const int tid = threadIdx.x;
    for (int i = tid; i < NUM_CLASSES * DIM; i += blockDim.x) Wcs[i] = Wc[i];
    if (tid < NUM_CLASSES) bcs[tid] = bc[tid];
    __syncthreads();

    const int lane = tid & 31;
    const int wid  = tid >> 5;
    const int node = blockIdx.x * (blockDim.x >> 5) + wid;
    if (node >= N_NODES) return;

    const int s = rs[node];
    const int e = rs[node + 1];
    float4 h = gather_row(esrc, y, s, e, lane * 4);

    h.x = fmaxf(h.x, 0.f); h.y = fmaxf(h.y, 0.f);
    h.z = fmaxf(h.z, 0.f); h.w = fmaxf(h.w, 0.f);

    float sq = h.x * h.x + h.y * h.y + h.z * h.z + h.w * h.w;
    sq += __shfl_xor_sync(0xffffffff, sq, 16);
    sq += __shfl_xor_sync(0xffffffff, sq, 8);
    sq += __shfl_xor_sync(0xffffffff, sq, 4);
    sq += __shfl_xor_sync(0xffffffff, sq, 2);
    sq += __shfl_xor_sync(0xffffffff, sq, 1);
    float n = fmaxf(sqrtf(sq), EPSF);
    float f = atanhf(fminf(n, MAX_NORM)) / n;
    float4 t = make_float4(f * h.x, f * h.y, f * h.z, f * h.w);

#pragma unroll
    for (int c = 0; c < NUM_CLASSES; c++) {
        float4 w = *(const float4*)&Wcs[c * DIM + lane * 4];
        float p = t.x * w.x + t.y * w.y + t.z * w.z + t.w * w.w;
        p += __shfl_xor_sync(0xffffffff, p, 16);
        p += __shfl_xor_sync(0xffffffff, p, 8);
        p += __shfl_xor_sync(0xffffffff, p, 4);
        p += __shfl_xor_sync(0xffffffff, p, 2);
        p += __shfl_xor_sync(0xffffffff, p, 1);
        if (lane == 0) out[node * NUM_CLASSES + c] = p + bcs[c];
    }
}

// ---------------------------------------------------------------------------
// Fused: (optional relu) -> logmap0 -> h = t @ W^T + b -> expmap0
// 128 threads, BM=16 nodes/tile, persistent; packed f32x2 FMA inner loop.
// 3 blocks/SM for latency hiding.
__global__ void __launch_bounds__(128, 3)
transform_kernel(const float* __restrict__ in, const float* __restrict__ W,
                 const float* __restrict__ bias, float* __restrict__ out,
                 int do_relu) {
    extern __shared__ float sm[];
    float* Wsh = sm + SM_W;
    float* t2  = sm + SM_T2;
    float* red = sm + SM_RED;
    float* fac = sm + SM_FAC;

    const int tid  = threadIdx.x;
    const int lane = tid & 31;
    const int wid  = tid >> 5;

    // Load W transposed into smem: Wsh[k*129 + j] = W[j*128 + k]
    for (int idx = tid; idx < DIM * DIM; idx += 128) {
        int j = idx >> 7, k = idx & 127;
        Wsh[k * WPITCH + j] = W[idx];
    }
    const float bj = bias[tid];
    __syncthreads();

    const int ntiles = N_NODES / BM;   // 3125, exact
    for (int tile = blockIdx.x; tile < ntiles; tile += gridDim.x) {
        const int node0 = tile * BM;

        // ---- load inputs (thread tid owns column tid of all BM rows) ----
        float xv[BM];
#pragma unroll
        for (int r = 0; r < BM; r++) {
            float v = in[(node0 + r) * DIM + tid];
            if (do_relu) v = fmaxf(v, 0.f);
            xv[r] = v;
        }

        // ---- per-row sum of squares, reduced across 128 threads ----
        float ss[BM];
#pragma unroll
        for (int r = 0; r < BM; r++) {
            float s = xv[r] * xv[r];
            s += __shfl_xor_sync(0xffffffff, s, 16);
            s += __shfl_xor_sync(0xffffffff, s, 8);
            s += __shfl_xor_sync(0xffffffff, s, 4);
            s += __shfl_xor_sync(0xffffffff, s, 2);
            s += __shfl_xor_sync(0xffffffff, s, 1);
            ss[r] = s;
        }
        if (lane == 0) {
#pragma unroll
            for (int r = 0; r < BM; r++) red[wid * BM + r] = ss[r];
        }
        __syncthreads();
        if (tid < BM) {
            float s = red[0 * BM + tid] + red[1 * BM + tid] +
                      red[2 * BM + tid] + red[3 * BM + tid];
            float n = fmaxf(sqrtf(s), EPSF);
            fac[tid] = atanhf(fminf(n, MAX_NORM)) / n;   // logmap0 factor
        }
        __syncthreads();

        // ---- write t transposed: t2[k=tid][r], float4-packed ----
#pragma unroll
        for (int q = 0; q < 4; q++) {
            float4 tv;
            tv.x = xv[4 * q + 0] * fac[4 * q + 0];
            tv.y = xv[4 * q + 1] * fac[4 * q + 1];
            tv.z = xv[4 * q + 2] * fac[4 * q + 2];
            tv.w = xv[4 * q + 3] * fac[4 * q + 3];
            *(float4*)&t2[tid * TPITCH + 4 * q] = tv;
        }
        __syncthreads();

        // ---- GEMM inner loop (packed f32x2): thread tid = output column tid
        u64 acc2[8];
#pragma unroll
        for (int j = 0; j < 8; j++) acc2[j] = 0ULL;

#pragma unroll 4
        for (int k = 0; k < DIM; k++) {
            float w = Wsh[k * WPITCH + tid];
            u64 ww = pack2(w, w);
            const float* trow = &t2[k * TPITCH];
            ulonglong2 p0 = *(const ulonglong2*)(trow + 0);
            ulonglong2 p1 = *(const ulonglong2*)(trow + 4);
            ulonglong2 p2 = *(const ulonglong2*)(trow + 8);
            ulonglong2 p3 = *(const ulonglong2*)(trow + 12);
            acc2[0] = fma2(ww, p0.x, acc2[0]);
            acc2[1] = fma2(ww, p0.y, acc2[1]);
            acc2[2] = fma2(ww, p1.x, acc2[2]);
            acc2[3] = fma2(ww, p1.y, acc2[3]);
            acc2[4] = fma2(ww, p2.x, acc2[4]);
            acc2[5] = fma2(ww, p2.y, acc2[5]);
            acc2[6] = fma2(ww, p3.x, acc2[6]);
            acc2[7] = fma2(ww, p3.y, acc2[7]);
        }

        // ---- epilogue: + bias, expmap0 ----
        float hv[BM];
#pragma unroll
        for (int j = 0; j < 8; j++) {
            float lo, hi;
            unpack2(acc2[j], lo, hi);
            hv[2 * j + 0] = lo + bj;
            hv[2 * j + 1] = hi + bj;
        }

#pragma unroll
        for (int r = 0; r < BM; r++) {
            float s = hv[r] * hv[r];
            s += __shfl_xor_sync(0xffffffff, s, 16);
            s += __shfl_xor_sync(0xffffffff, s, 8);
            s += __shfl_xor_sync(0xffffffff, s, 4);
            s += __shfl_xor_sync(0xffffffff, s, 2);
            s += __shfl_xor_sync(0xffffffff, s, 1);
            ss[r] = s;
        }
        __syncthreads();   // protect red[] against stragglers of prior phase
        if (lane == 0) {
#pragma unroll
            for (int r = 0; r < BM; r++) red[wid * BM + r] = ss[r];
        }
        __syncthreads();
        if (tid < BM) {
            float s = red[0 * BM + tid] + red[1 * BM + tid] +
                      red[2 * BM + tid] + red[3 * BM + tid];
            float n = fmaxf(sqrtf(s), EPSF);
            fac[tid] = tanhf(n) / n;                     // expmap0 factor
        }
        __syncthreads();

#pragma unroll
        for (int r = 0; r < BM; r++)
            out[(node0 + r) * DIM + tid] = fac[r] * hv[r];
        __syncthreads();   // fac/red reused next tile
    }
}

// ---------------------------------------------------------------------------
extern "C" void kernel_launch(void* const* d_in, const int* in_sizes, int n_in,
                              void* d_out, int out_size) {
    const int*   e32 = (const int*)d_in[0];
    const float* x   = (const float*)d_in[1];
    const float* W1  = (const float*)d_in[2];
    const float* b1  = (const float*)d_in[3];
    const float* W2  = (const float*)d_in[4];
    const float* b2  = (const float*)d_in[5];
    const float* Wc  = (const float*)d_in[6];
    const float* bc  = (const float*)d_in[7];
    float* out = (float*)d_out;

    float *y, *agg;
    int *rs, *es;
    cudaGetSymbolAddress((void**)&y,   g_y);
    cudaGetSymbolAddress((void**)&agg, g_agg);
    cudaGetSymbolAddress((void**)&rs,  g_rowstart);
    cudaGetSymbolAddress((void**)&es,  g_esrc);

    cudaFuncSetAttribute(transform_kernel,
                         cudaFuncAttributeMaxDynamicSharedMemorySize, SMEM_BYTES);

    const int gblocks = (N_NODES + 7) / 8;     // 8 warps/block

    // layer 1 transform is independent of the CSR build
    transform_kernel<<<444, 128, SMEM_BYTES>>>(x, W1, b1, y, 0);
    csr_kernel<<<CSR_BLOCKS, CSR_THREADS>>>(e32);
    gather_kernel<<<gblocks, 256>>>(es, rs, y, agg);
    transform_kernel<<<444, 128, SMEM_BYTES>>>(agg, W2, b2, y, 1);
    gather_cls_kernel<<<gblocks, 256>>>(es, rs, y, Wc, bc, out);
}

// round 6
// speedup vs baseline: 1.1254x; 1.1077x over previous
#include <cuda_runtime.h>
#include <cuda_bf16.h>
#include <math.h>

#define N_NODES 50000
#define N_EDGES 600000
#define DIM 128
#define NUM_CLASSES 10
#define EPSF 1e-15f
#define MAX_NORM (1.0f - 1e-5f)

#define XT_PITCH 50048             // padded so every 64-node tile read is in-bounds
#define FT_PITCH 129               // facT smem tile pitch (conflict-free)
#define MM_TILES ((N_NODES + 63) / 64)   // 782
#define MM_GRID 296
#define MM_SMEM ((DIM * DIM + DIM * 64) * 4)   // Wsh 64KB + t2 32KB

#define CSR_BLOCKS 49
#define CSR_THREADS 1024

typedef unsigned long long u64;

// scratch (device globals: no allocation allowed)
__device__ float g_y[N_NODES * DIM];
__device__ float g_agg[N_NODES * DIM];
__device__ float g_xT[DIM * XT_PITCH];
__device__ int   g_mult;
__device__ int   g_count[N_NODES];
__device__ int   g_cursor[N_NODES];
__device__ int   g_rowstart[N_NODES + 1];
__device__ int   g_bsum[CSR_BLOCKS];
__device__ volatile unsigned g_bar_gen;   // monotonic across graph replays
__device__ unsigned g_bar_cnt;            // self-resets
__device__ int   g_esrc[N_EDGES];

// ---------------------------------------------------------------------------
// packed fp32x2 helpers (Blackwell dual-rate FFMA2 — PTX-only)
__device__ __forceinline__ u64 fma2(u64 a, u64 b, u64 c) {
    u64 d;
    asm("fma.rn.f32x2 %0, %1, %2, %3;" : "=l"(d) : "l"(a), "l"(b), "l"(c));
    return d;
}
__device__ __forceinline__ u64 add2(u64 a, u64 b) {
    u64 d;
    asm("add.rn.f32x2 %0, %1, %2;" : "=l"(d) : "l"(a), "l"(b));
    return d;
}
__device__ __forceinline__ u64 mul2(u64 a, u64 b) {
    u64 d;
    asm("mul.rn.f32x2 %0, %1, %2;" : "=l"(d) : "l"(a), "l"(b));
    return d;
}
__device__ __forceinline__ u64 pack2(float lo, float hi) {
    u64 r;
    asm("mov.b64 %0, {%1, %2};" : "=l"(r) : "f"(lo), "f"(hi));
    return r;
}
__device__ __forceinline__ void unpack2(u64 v, float& lo, float& hi) {
    asm("mov.b64 {%0, %1}, %2;" : "=f"(lo), "=f"(hi) : "l"(v));
}

// ---------------------------------------------------------------------------
// software grid barrier (all CSR_BLOCKS resident: 49 << 148 SMs)
__device__ __forceinline__ void grid_barrier() {
    __syncthreads();
    if (threadIdx.x == 0) {
        __threadfence();
        unsigned my = g_bar_gen;
        unsigned a = atomicAdd(&g_bar_cnt, 1);
        if (a == CSR_BLOCKS - 1) {
            g_bar_cnt = 0;
            __threadfence();
            g_bar_gen = my + 1;
        } else {
            while (g_bar_gen == my) __nanosleep(32);
        }
    }
    __syncthreads();
}

// ---------------------------------------------------------------------------
// Fused CSR build: detect dtype + zero hist + hist + scan + bucket scatter.
__global__ void __launch_bounds__(CSR_THREADS)
csr_kernel(const int* __restrict__ e32) {
    const int b = blockIdx.x, t = threadIdx.x;
    const int gid = b * CSR_THREADS + t;
    const int nth = CSR_BLOCKS * CSR_THREADS;

    if (b == 0 && t < 32) {
        int v1 = e32[2 * t + 1];
        int bad = __any_sync(0xffffffffu, v1 != 0);
        if (t == 0) g_mult = bad ? 1 : 2;
    }
    if (gid < N_NODES) g_count[gid] = 0;
    grid_barrier();

    const int m = g_mult;
    for (int e = gid; e < N_EDGES; e += nth) {
        int dst = e32[(long long)(N_EDGES + e) * m];
        atomicAdd(&g_count[dst], 1);
    }
    grid_barrier();

    __shared__ int wsum[32];
    __shared__ int part[2];
    const int lane = t & 31, w = t >> 5;
    int v = (gid < N_NODES) ? g_count[gid] : 0;
    int x = v;
#pragma unroll
    for (int d = 1; d < 32; d <<= 1) {
        int y = __shfl_up_sync(0xffffffffu, x, d);
        if (lane >= d) x += y;
    }
    if (lane == 31) wsum[w] = x;
    __syncthreads();
    if (w == 0) {
        int s = wsum[lane];
#pragma unroll
        for (int d = 1; d < 32; d <<= 1) {
            int y = __shfl_up_sync(0xffffffffu, s, d);
            if (lane >= d) s += y;
        }
        wsum[lane] = s;
    }
    __syncthreads();
    int excl = x - v + (w ? wsum[w - 1] : 0);
    if (t == CSR_THREADS - 1) g_bsum[b] = excl + v;
    grid_barrier();

    if (t < 64) {
        int pv = (t < b) ? g_bsum[t] : 0;
#pragma unroll
        for (int d = 16; d > 0; d >>= 1)
            pv += __shfl_xor_sync(0xffffffffu, pv, d);
        if (lane == 0) part[w] = pv;
    }
    __syncthreads();
    const int boff = part[0] + part[1];
    if (gid < N_NODES) {
        int rv = excl + boff;
        g_rowstart[gid] = rv;
        g_cursor[gid] = rv;
    }
    if (gid == 0) g_rowstart[N_NODES] = N_EDGES;
    grid_barrier();

    for (int e = gid; e < N_EDGES; e += nth) {
        int src = e32[(long long)e * m];
        int dst = e32[(long long)(N_EDGES + e) * m];
        int pos = atomicAdd(&g_cursor[dst], 1);
        g_esrc[pos] = src;
    }
}

// ---------------------------------------------------------------------------
// facT: 32-node tile -> (optional per-node logmap0 factor) -> transposed write.
// do_norm=1: xT[f][n] = atanh_factor(n) * in[n][f]; do_norm=0: pure transpose.
__global__ void __launch_bounds__(256)
facT_kernel(const float* __restrict__ in, float* __restrict__ xT, int do_norm) {
    __shared__ float s[32 * FT_PITCH];
    __shared__ float facs[32];
    const int tid = threadIdx.x, lane = tid & 31, w = tid >> 5;
    const int node0 = blockIdx.x * 32;

    // stage tile (coalesced LDG.128; 4 STS.32 row-contiguous, conflict-free)
#pragma unroll
    for (int q = 0; q < 4; q++) {
        int idx = q * 256 + tid;          // 0..1023 float4s
        int n = idx >> 5, c4 = idx & 31;
        float4 v = make_float4(0.f, 0.f, 0.f, 0.f);
        if (node0 + n < N_NODES)
            v = __ldg((const float4*)&in[(node0 + n) * DIM + c4 * 4]);
        float* sr = &s[n * FT_PITCH + c4 * 4];
        sr[0] = v.x; sr[1] = v.y; sr[2] = v.z; sr[3] = v.w;
    }
    __syncthreads();

    if (do_norm) {
        // warp w: nodes 4w..4w+3; stride-1 LDS reads, conflict-free
#pragma unroll
        for (int j = 0; j < 4; j++) {
            int n = w * 4 + j;
            const float* sr = &s[n * FT_PITCH];
            float a0 = sr[lane], a1 = sr[lane + 32];
            float a2 = sr[lane + 64], a3 = sr[lane + 96];
            float ss = a0 * a0 + a1 * a1 + a2 * a2 + a3 * a3;
            ss += __shfl_xor_sync(0xffffffff, ss, 16);
            ss += __shfl_xor_sync(0xffffffff, ss, 8);
            ss += __shfl_xor_sync(0xffffffff, ss, 4);
            ss += __shfl_xor_sync(0xffffffff, ss, 2);
            ss += __shfl_xor_sync(0xffffffff, ss, 1);
            if (lane == 0) {
                float nn = fmaxf(sqrtf(ss), EPSF);
                facs[n] = atanhf(fminf(nn, MAX_NORM)) / nn;
            }
        }
    } else {
        if (tid < 32) facs[tid] = 1.0f;
    }
    __syncthreads();

    // transposed write: warp w writes feature rows w, w+8, ...; lane = node
    const int n = node0 + lane;
    const bool ok = n < N_NODES;
    const float fl = facs[lane];
#pragma unroll
    for (int f = 0; f < DIM; f += 8) {
        int row = f + w;
        float v = s[lane * FT_PITCH + row];   // stride-129: conflict-free
        if (ok) xT[row * XT_PITCH + n] = fl * v;
    }
}

// ---------------------------------------------------------------------------
// mm: y = expmap0( t @ W^T + b ), t read feature-major from xT.
// Persistent; W in smem once per block; 64-node tiles; warp = 8 nodes x 128 cols;
// thread = 4 cols x 8 nodes (4 f32x2 node-pairs).
__global__ void __launch_bounds__(256, 2)
mm_kernel(const float* __restrict__ xT, const float* __restrict__ W,
          const float* __restrict__ bias, float* __restrict__ y) {
    extern __shared__ float sm[];
    float* Wsh = sm;               // [k][j], 128x128
    float* t2  = sm + DIM * DIM;   // [k][n], 128x64

    const int tid = threadIdx.x, lane = tid & 31, w = tid >> 5;

    // Wsh[k*128 + j] = W[j*128 + k]  (one-time; persistent amortizes conflicts)
    for (int idx = tid; idx < DIM * DIM; idx += 256) {
        int j = idx >> 7, k = idx & 127;
        Wsh[k * DIM + j] = W[idx];
    }
    const float4 bv = __ldg((const float4*)&bias[4 * lane]);
    const u64 bb0 = pack2(bv.x, bv.x), bb1 = pack2(bv.y, bv.y);
    const u64 bb2 = pack2(bv.z, bv.z), bb3 = pack2(bv.w, bv.w);
    __syncthreads();

    for (int tile = blockIdx.x; tile < MM_TILES; tile += gridDim.x) {
        const int n0 = tile * 64;

        // stage t2[k][0..63] from xT rows (coalesced, conflict-free)
#pragma unroll
        for (int q = 0; q < 8; q++) {
            int idx = q * 256 + tid;          // 0..2047 float4s
            int k = idx >> 4, c4 = idx & 15;
            float4 v = *(const float4*)&xT[k * XT_PITCH + n0 + c4 * 4];
            *(float4*)&t2[k * 64 + c4 * 4] = v;
        }
        __syncthreads();

        u64 acc[4][4];
#pragma unroll
        for (int c = 0; c < 4; c++)
#pragma unroll
            for (int p = 0; p < 4; p++) acc[c][p] = 0ULL;

#pragma unroll 8
        for (int k = 0; k < DIM; k++) {
            float4 wv = *(const float4*)&Wsh[k * DIM + 4 * lane];
            u64 w0 = pack2(wv.x, wv.x), w1 = pack2(wv.y, wv.y);
            u64 w2 = pack2(wv.z, wv.z), w3 = pack2(wv.w, wv.w);
            const ulonglong2* tp = (const ulonglong2*)&t2[k * 64 + 8 * w];
            ulonglong2 ta = tp[0], tb = tp[1];
            acc[0][0] = fma2(w0, ta.x, acc[0][0]);
            acc[1][0] = fma2(w1, ta.x, acc[1][0]);
            acc[2][0] = fma2(w2, ta.x, acc[2][0]);
            acc[3][0] = fma2(w3, ta.x, acc[3][0]);
            acc[0][1] = fma2(w0, ta.y, acc[0][1]);
            acc[1][1] = fma2(w1, ta.y, acc[1][1]);
            acc[2][1] = fma2(w2, ta.y, acc[2][1]);
            acc[3][1] = fma2(w3, ta.y, acc[3][1]);
            acc[0][2] = fma2(w0, tb.x, acc[0][2]);
            acc[1][2] = fma2(w1, tb.x, acc[1][2]);
            acc[2][2] = fma2(w2, tb.x, acc[2][2]);
            acc[3][2] = fma2(w3, tb.x, acc[3][2]);
            acc[0][3] = fma2(w0, tb.y, acc[0][3]);
            acc[1][3] = fma2(w1, tb.y, acc[1][3]);
            acc[2][3] = fma2(w2, tb.y, acc[2][3]);
            acc[3][3] = fma2(w3, tb.y, acc[3][3]);
        }

        // epilogue: +bias, expmap0 per node, store
#pragma unroll
        for (int p = 0; p < 4; p++) {
            u64 h0 = add2(acc[0][p], bb0);
            u64 h1 = add2(acc[1][p], bb1);
            u64 h2 = add2(acc[2][p], bb2);
            u64 h3 = add2(acc[3][p], bb3);
            u64 ss = fma2(h0, h0, fma2(h1, h1, fma2(h2, h2, mul2(h3, h3))));
#pragma unroll
            for (int d = 16; d > 0; d >>= 1)
                ss = add2(ss, __shfl_xor_sync(0xffffffffu, ss, d));
            float slo, shi;
            unpack2(ss, slo, shi);
            float nlo = fmaxf(sqrtf(slo), EPSF);
            float nhi = fmaxf(sqrtf(shi), EPSF);
            u64 fp = pack2(tanhf(nlo) / nlo, tanhf(nhi) / nhi);
            u64 m0 = mul2(fp, h0), m1 = mul2(fp, h1);
            u64 m2 = mul2(fp, h2), m3 = mul2(fp, h3);
            float l0, u0, l1, u1, l2, u2, l3, u3;
            unpack2(m0, l0, u0); unpack2(m1, l1, u1);
            unpack2(m2, l2, u2); unpack2(m3, l3, u3);
            int nA = n0 + 8 * w + 2 * p;
            if (nA < N_NODES) {
                float4 o = make_float4(l0, l1, l2, l3);
                *(float4*)&y[nA * DIM + 4 * lane] = o;
            }
            if (nA + 1 < N_NODES) {
                float4 o = make_float4(u0, u1, u2, u3);
                *(float4*)&y[(nA + 1) * DIM + 4 * lane] = o;
            }
        }
        __syncthreads();   // t2 reuse next tile
    }
}

// ---------------------------------------------------------------------------
// Warp-level CSR row gather with 4-deep MLP. Returns per-lane float4 sum.
__device__ __forceinline__ float4 gather_row(const int* __restrict__ esrc,
                                             const float* __restrict__ y,
                                             int s, int e, int lane4) {
    float4 a0 = make_float4(0.f, 0.f, 0.f, 0.f);
    float4 a1 = make_float4(0.f, 0.f, 0.f, 0.f);
    float4 a2 = make_float4(0.f, 0.f, 0.f, 0.f);
    float4 a3 = make_float4(0.f, 0.f, 0.f, 0.f);
    int i = s;
    for (; i + 4 <= e; i += 4) {
        int s0 = __ldg(&esrc[i + 0]);
        int s1 = __ldg(&esrc[i + 1]);
        int s2 = __ldg(&esrc[i + 2]);
        int s3 = __ldg(&esrc[i + 3]);
        float4 v0 = __ldg((const float4*)&y[s0 * DIM + lane4]);
        float4 v1 = __ldg((const float4*)&y[s1 * DIM + lane4]);
        float4 v2 = __ldg((const float4*)&y[s2 * DIM + lane4]);
        float4 v3 = __ldg((const float4*)&y[s3 * DIM + lane4]);
        a0.x += v0.x; a0.y += v0.y; a0.z += v0.z; a0.w += v0.w;
        a1.x += v1.x; a1.y += v1.y; a1.z += v1.z; a1.w += v1.w;
        a2.x += v2.x; a2.y += v2.y; a2.z += v2.z; a2.w += v2.w;
        a3.x += v3.x; a3.y += v3.y; a3.z += v3.z; a3.w += v3.w;
    }
    if (i + 2 <= e) {
        int s0 = __ldg(&esrc[i + 0]);
        int s1 = __ldg(&esrc[i + 1]);
        float4 v0 = __ldg((const float4*)&y[s0 * DIM + lane4]);
        float4 v1 = __ldg((const float4*)&y[s1 * DIM + lane4]);
        a0.x += v0.x; a0.y += v0.y; a0.z += v0.z; a0.w += v0.w;
        a1.x += v1.x; a1.y += v1.y; a1.z += v1.z; a1.w += v1.w;
        i += 2;
    }
    if (i < e) {
        int s0 = __ldg(&esrc[i]);
        float4 v0 = __ldg((const float4*)&y[s0 * DIM + lane4]);
        a0.x += v0.x; a0.y += v0.y; a0.z += v0.z; a0.w += v0.w;
    }
    float4 r;
    r.x = (a0.x + a1.x) + (a2.x + a3.x);
    r.y = (a0.y + a1.y) + (a2.y + a3.y);
    r.z = (a0.z + a1.z) + (a2.z + a3.z);
    r.w = (a0.w + a1.w) + (a2.w + a3.w);
    return r;
}

// Layer-1 aggregation fused with relu + logmap0 scaling (layer-2 pre-transform):
// agg[n] = atanh_factor(relu(sum)) * relu(sum)
__global__ void __launch_bounds__(256)
gather_kernel(const int* __restrict__ esrc, const int* __restrict__ rs,
              const float* __restrict__ y, float* __restrict__ agg) {
    const int lane = threadIdx.x & 31;
    const int wid  = threadIdx.x >> 5;
    const int node = blockIdx.x * (blockDim.x >> 5) + wid;
    if (node >= N_NODES) return;
    const int s = rs[node];
    const int e = rs[node + 1];
    float4 r = gather_row(esrc, y, s, e, lane * 4);

    r.x = fmaxf(r.x, 0.f); r.y = fmaxf(r.y, 0.f);
    r.z = fmaxf(r.z, 0.f); r.w = fmaxf(r.w, 0.f);

    float ss = r.x * r.x + r.y * r.y + r.z * r.z + r.w * r.w;
    ss += __shfl_xor_sync(0xffffffff, ss, 16);
    ss += __shfl_xor_sync(0xffffffff, ss, 8);
    ss += __shfl_xor_sync(0xffffffff, ss, 4);
    ss += __shfl_xor_sync(0xffffffff, ss, 2);
    ss += __shfl_xor_sync(0xffffffff, ss, 1);
    float n = fmaxf(sqrtf(ss), EPSF);
    float f = atanhf(fminf(n, MAX_NORM)) / n;

    float4 o = make_float4(f * r.x, f * r.y, f * r.z, f * r.w);
    *(float4*)&agg[node * DIM + lane * 4] = o;
}

// Layer-2 aggregation fused with classifier: gather -> relu -> logmap0 -> Wc
__global__ void __launch_bounds__(256)
gather_cls_kernel(const int* __restrict__ esrc, const int* __restrict__ rs,
                  const float* __restrict__ y, const float* __restrict__ Wc,
                  const float* __restrict__ bc, float* __restrict__ out) {
    __shared__ float Wcs[NUM_CLASSES * DIM];
    __shared__ float bcs[NUM_CLASSES];
    const int tid = threadIdx.x;
    for (int i = tid; i < NUM_CLASSES * DIM; i += blockDim.x) Wcs[i] = Wc[i];
    if (tid < NUM_CLASSES) bcs[tid] = bc[tid];
    __syncthreads();

    const int lane = tid & 31;
    const int wid  = tid >> 5;
    const int node = blockIdx.x * (blockDim.x >> 5) + wid;
    if (node >= N_NODES) return;

    const int s = rs[node];
    const int e = rs[node + 1];
    float4 h = gather_row(esrc, y, s, e, lane * 4);

    h.x = fmaxf(h.x, 0.f); h.y = fmaxf(h.y, 0.f);
    h.z = fmaxf(h.z, 0.f); h.w = fmaxf(h.w, 0.f);

    float sq = h.x * h.x + h.y * h.y + h.z * h.z + h.w * h.w;
    sq += __shfl_xor_sync(0xffffffff, sq, 16);
    sq += __shfl_xor_sync(0xffffffff, sq, 8);
    sq += __shfl_xor_sync(0xffffffff, sq, 4);
    sq += __shfl_xor_sync(0xffffffff, sq, 2);
    sq += __shfl_xor_sync(0xffffffff, sq, 1);
    float n = fmaxf(sqrtf(sq), EPSF);
    float f = atanhf(fminf(n, MAX_NORM)) / n;
    float4 t = make_float4(f * h.x, f * h.y, f * h.z, f * h.w);

#pragma unroll
    for (int c = 0; c < NUM_CLASSES; c++) {
        float4 w = *(const float4*)&Wcs[c * DIM + lane * 4];
        float p = t.x * w.x + t.y * w.y + t.z * w.z + t.w * w.w;
        p += __shfl_xor_sync(0xffffffff, p, 16);
        p += __shfl_xor_sync(0xffffffff, p, 8);
        p += __shfl_xor_sync(0xffffffff, p, 4);
        p += __shfl_xor_sync(0xffffffff, p, 2);
        p += __shfl_xor_sync(0xffffffff, p, 1);
        if (lane == 0) out[node * NUM_CLASSES + c] = p + bcs[c];
    }
}

// ---------------------------------------------------------------------------
extern "C" void kernel_launch(void* const* d_in, const int* in_sizes, int n_in,
                              void* d_out, int out_size) {
    const int*   e32 = (const int*)d_in[0];
    const float* x   = (const float*)d_in[1];
    const float* W1  = (const float*)d_in[2];
    const float* b1  = (const float*)d_in[3];
    const float* W2  = (const float*)d_in[4];
    const float* b2  = (const float*)d_in[5];
    const float* Wc  = (const float*)d_in[6];
    const float* bc  = (const float*)d_in[7];
    float* out = (float*)d_out;

    float *y, *agg, *xT;
    int *rs, *es;
    cudaGetSymbolAddress((void**)&y,   g_y);
    cudaGetSymbolAddress((void**)&agg, g_agg);
    cudaGetSymbolAddress((void**)&xT,  g_xT);
    cudaGetSymbolAddress((void**)&rs,  g_rowstart);
    cudaGetSymbolAddress((void**)&es,  g_esrc);

    cudaFuncSetAttribute(mm_kernel,
                         cudaFuncAttributeMaxDynamicSharedMemorySize, MM_SMEM);

    const int ftblocks = (N_NODES + 31) / 32;   // 1563
    const int gblocks  = (N_NODES + 7) / 8;     // 8 warps/block

    // layer 1 (facT1/mm1 independent of CSR build)
    facT_kernel<<<ftblocks, 256>>>(x, xT, 1);
    csr_kernel<<<CSR_BLOCKS, CSR_THREADS>>>(e32);
    mm_kernel<<<MM_GRID, 256, MM_SMEM>>>(xT, W1, b1, y);
    gather_kernel<<<gblocks, 256>>>(es, rs, y, agg);   // + relu + logmap0
    // layer 2
    facT_kernel<<<ftblocks, 256>>>(agg, xT, 0);        // pure transpose
    mm_kernel<<<MM_GRID, 256, MM_SMEM>>>(xT, W2, b2, y);
    gather_cls_kernel<<<gblocks, 256>>>(es, rs, y, Wc, bc, out);
}

// round 7
// speedup vs baseline: 1.2220x; 1.0858x over previous
#include <cuda_runtime.h>
#include <cuda_bf16.h>
#include <math.h>

#define N_NODES 50000
#define N_EDGES 600000
#define DIM 128
#define NUM_CLASSES 10
#define EPSF 1e-15f
#define MAX_NORM (1.0f - 1e-5f)

#define KP 64                      // k-pairs
#define XTP 50048                  // node pitch for pair-packed xT (64*782)
#define FT_PITCH 129
#define MM_TILES ((N_NODES + 63) / 64)   // 782
#define MM_GRID 296
#define MM_SMEM ((KP * DIM + KP * 64) * 8)   // Wsh 64KB + Tsh 32KB = 96KB

#define CSR_BLOCKS 49
#define CSR_THREADS 1024

typedef unsigned long long u64;

// scratch (device globals: no allocation allowed)
__device__ float g_y[N_NODES * DIM];
__device__ float g_agg[N_NODES * DIM];
__device__ u64   g_xTp[KP * XTP];        // (t[2kp][n], t[2kp+1][n])
__device__ u64   g_Wp1[KP * DIM];        // (W[j][2kp], W[j][2kp+1]) at [kp*128+j]
__device__ u64   g_Wp2[KP * DIM];
__device__ int   g_mult;
__device__ int   g_count[N_NODES];
__device__ int   g_cursor[N_NODES];
__device__ int   g_rowstart[N_NODES + 1];
__device__ int   g_bsum[CSR_BLOCKS];
__device__ volatile unsigned g_bar_gen;   // monotonic across graph replays
__device__ unsigned g_bar_cnt;            // self-resets
__device__ int   g_esrc[N_EDGES];

// ---------------------------------------------------------------------------
// packed fp32x2 helpers (Blackwell FFMA2 — PTX-only)
__device__ __forceinline__ u64 fma2(u64 a, u64 b, u64 c) {
    u64 d;
    asm("fma.rn.f32x2 %0, %1, %2, %3;" : "=l"(d) : "l"(a), "l"(b), "l"(c));
    return d;
}
__device__ __forceinline__ u64 pack2(float lo, float hi) {
    u64 r;
    asm("mov.b64 %0, {%1, %2};" : "=l"(r) : "f"(lo), "f"(hi));
    return r;
}
__device__ __forceinline__ void unpack2(u64 v, float& lo, float& hi) {
    asm("mov.b64 {%0, %1}, %2;" : "=f"(lo), "=f"(hi) : "l"(v));
}
__device__ __forceinline__ float sum2(u64 v) {
    float lo, hi;
    unpack2(v, lo, hi);
    return lo + hi;
}

// ---------------------------------------------------------------------------
// software grid barrier (all CSR_BLOCKS resident: 49 << 148 SMs)
__device__ __forceinline__ void grid_barrier() {
    __syncthreads();
    if (threadIdx.x == 0) {
        __threadfence();
        unsigned my = g_bar_gen;
        unsigned a = atomicAdd(&g_bar_cnt, 1);
        if (a == CSR_BLOCKS - 1) {
            g_bar_cnt = 0;
            __threadfence();
            g_bar_gen = my + 1;
        } else {
            while (g_bar_gen == my) __nanosleep(32);
        }
    }
    __syncthreads();
}

// ---------------------------------------------------------------------------
// Fused CSR build (side stream): detect + zero + hist + scan + bucket scatter.
__global__ void __launch_bounds__(CSR_THREADS)
csr_kernel(const int* __restrict__ e32) {
    const int b = blockIdx.x, t = threadIdx.x;
    const int gid = b * CSR_THREADS + t;
    const int nth = CSR_BLOCKS * CSR_THREADS;

    if (b == 0 && t < 32) {
        int v1 = e32[2 * t + 1];
        int bad = __any_sync(0xffffffffu, v1 != 0);
        if (t == 0) g_mult = bad ? 1 : 2;
    }
    if (gid < N_NODES) g_count[gid] = 0;
    grid_barrier();

    const int m = g_mult;
    for (int e = gid; e < N_EDGES; e += nth) {
        int dst = e32[(long long)(N_EDGES + e) * m];
        atomicAdd(&g_count[dst], 1);
    }
    grid_barrier();

    __shared__ int wsum[32];
    __shared__ int part[2];
    const int lane = t & 31, w = t >> 5;
    int v = (gid < N_NODES) ? g_count[gid] : 0;
    int x = v;
#pragma unroll
    for (int d = 1; d < 32; d <<= 1) {
        int y = __shfl_up_sync(0xffffffffu, x, d);
        if (lane >= d) x += y;
    }
    if (lane == 31) wsum[w] = x;
    __syncthreads();
    if (w == 0) {
        int s = wsum[lane];
#pragma unroll
        for (int d = 1; d < 32; d <<= 1) {
            int y = __shfl_up_sync(0xffffffffu, s, d);
            if (lane >= d) s += y;
        }
        wsum[lane] = s;
    }
    __syncthreads();
    int excl = x - v + (w ? wsum[w - 1] : 0);
    if (t == CSR_THREADS - 1) g_bsum[b] = excl + v;
    grid_barrier();

    if (t < 64) {
        int pv = (t < b) ? g_bsum[t] : 0;
#pragma unroll
        for (int d = 16; d > 0; d >>= 1)
            pv += __shfl_xor_sync(0xffffffffu, pv, d);
        if (lane == 0) part[w] = pv;
    }
    __syncthreads();
    const int boff = part[0] + part[1];
    if (gid < N_NODES) {
        int rv = excl + boff;
        g_rowstart[gid] = rv;
        g_cursor[gid] = rv;
    }
    if (gid == 0) g_rowstart[N_NODES] = N_EDGES;
    grid_barrier();

    for (int e = gid; e < N_EDGES; e += nth) {
        int src = e32[(long long)e * m];
        int dst = e32[(long long)(N_EDGES + e) * m];
        int pos = atomicAdd(&g_cursor[dst], 1);
        g_esrc[pos] = src;
    }
}

// ---------------------------------------------------------------------------
// wprep: transpose W1,W2 into k-pair layout Wp[kp*128 + j] = (W[j][2kp], W[j][2kp+1])
__global__ void __launch_bounds__(256)
wprep_kernel(const float* __restrict__ W1, const float* __restrict__ W2,
             u64* __restrict__ Wp1, u64* __restrict__ Wp2) {
    __shared__ float s[32 * FT_PITCH];
    const int mtx = blockIdx.x >> 2;
    const int j0 = (blockIdx.x & 3) * 32;
    const float* W = mtx ? W2 : W1;
    u64* Wp = mtx ? Wp2 : Wp1;
    const int tid = threadIdx.x;

#pragma unroll
    for (int q = 0; q < 4; q++) {
        int idx = q * 256 + tid;          // 0..1023 float4s
        int jj = idx >> 5, k4 = idx & 31;
        float4 v = __ldg((const float4*)&W[(j0 + jj) * DIM + k4 * 4]);
        float* sr = &s[jj * FT_PITCH + k4 * 4];
        sr[0] = v.x; sr[1] = v.y; sr[2] = v.z; sr[3] = v.w;
    }
    __syncthreads();
#pragma unroll
    for (int q = 0; q < 8; q++) {
        int idx = q * 256 + tid;          // 0..2047
        int kp = idx >> 5, jj = idx & 31;
        Wp[kp * DIM + j0 + jj] =
            pack2(s[jj * FT_PITCH + 2 * kp], s[jj * FT_PITCH + 2 * kp + 1]);
    }
}

// ---------------------------------------------------------------------------
// facT: 32-node tile -> (optional logmap0 factor) -> k-pair transposed write.
__global__ void __launch_bounds__(256)
facT_kernel(const float* __restrict__ in, u64* __restrict__ xTp, int do_norm) {
    __shared__ float s[32 * FT_PITCH];
    __shared__ float facs[32];
    const int tid = threadIdx.x, lane = tid & 31, w = tid >> 5;
    const int node0 = blockIdx.x * 32;

#pragma unroll
    for (int q = 0; q < 4; q++) {
        int idx = q * 256 + tid;
        int n = idx >> 5, c4 = idx & 31;
        float4 v = make_float4(0.f, 0.f, 0.f, 0.f);
        if (node0 + n < N_NODES)
            v = __ldg((const float4*)&in[(node0 + n) * DIM + c4 * 4]);
        float* sr = &s[n * FT_PITCH + c4 * 4];
        sr[0] = v.x; sr[1] = v.y; sr[2] = v.z; sr[3] = v.w;
    }
    __syncthreads();

    if (do_norm) {
#pragma unroll
        for (int j = 0; j < 4; j++) {
            int n = w * 4 + j;
            const float* sr = &s[n * FT_PITCH];
            float a0 = sr[lane], a1 = sr[lane + 32];
            float a2 = sr[lane + 64], a3 = sr[lane + 96];
            float ss = a0 * a0 + a1 * a1 + a2 * a2 + a3 * a3;
            ss += __shfl_xor_sync(0xffffffff, ss, 16);
            ss += __shfl_xor_sync(0xffffffff, ss, 8);
            ss += __shfl_xor_sync(0xffffffff, ss, 4);
            ss += __shfl_xor_sync(0xffffffff, ss, 2);
            ss += __shfl_xor_sync(0xffffffff, ss, 1);
            if (lane == 0) {
                float nn = fmaxf(sqrtf(ss), EPSF);
                facs[n] = atanhf(fminf(nn, MAX_NORM)) / nn;
            }
        }
    } else {
        if (tid < 32) facs[tid] = 1.0f;
    }
    __syncthreads();

    const int n = node0 + lane;
    const bool ok = n < N_NODES;
    const float fl = facs[lane];
#pragma unroll
    for (int i = 0; i < 8; i++) {
        int kp = w + 8 * i;
        float vlo = fl * s[lane * FT_PITCH + 2 * kp];
        float vhi = fl * s[lane * FT_PITCH + 2 * kp + 1];
        if (ok) xTp[kp * XTP + n] = pack2(vlo, vhi);
    }
}

// ---------------------------------------------------------------------------
// mm: y = expmap0( t @ W^T + b ). k-pair packed operands: fma2 halves carry
// even/odd-k partial sums; no operand duplication MOVs in the inner loop.
// Persistent; 64-node tiles; warp = 8 nodes; thread = 4 cols x 8 nodes.
__global__ void __launch_bounds__(256, 2)
mm_kernel(const u64* __restrict__ xTp, const u64* __restrict__ Wp,
          const float* __restrict__ bias, float* __restrict__ y) {
    extern __shared__ u64 sm8[];
    u64* Wsh = sm8;                // [kp][j], 64x128
    u64* Tsh = sm8 + KP * DIM;     // [kp][n], 64x64

    const int tid = threadIdx.x, lane = tid & 31, w = tid >> 5;

    {
        const ulonglong2* wg = (const ulonglong2*)Wp;
        ulonglong2* ws = (ulonglong2*)Wsh;
        for (int i = tid; i < KP * DIM / 2; i += 256) ws[i] = wg[i];
    }
    const float4 bv = __ldg((const float4*)&bias[4 * lane]);
    __syncthreads();

    for (int tile = blockIdx.x; tile < MM_TILES; tile += gridDim.x) {
        const int n0 = tile * 64;

        // stage Tsh (coalesced ulonglong2 copies)
#pragma unroll
        for (int q = 0; q < 8; q++) {
            int idx = q * 256 + tid;            // 0..2047 ulonglong2
            int kp = idx >> 5, c2 = idx & 31;
            *(ulonglong2*)&Tsh[kp * 64 + c2 * 2] =
                *(const ulonglong2*)&xTp[kp * XTP + n0 + c2 * 2];
        }
        __syncthreads();

        u64 acc[4][8];
#pragma unroll
        for (int c = 0; c < 4; c++)
#pragma unroll
            for (int p = 0; p < 8; p++) acc[c][p] = 0ULL;

#pragma unroll 2
        for (int kp = 0; kp < KP; kp++) {
            const u64* wrow = &Wsh[kp * DIM + 4 * lane];
            ulonglong2 wa = *(const ulonglong2*)wrow;        // cols j0,j1
            ulonglong2 wb = *(const ulonglong2*)(wrow + 2);  // cols j2,j3
            const ulonglong2* tp = (const ulonglong2*)&Tsh[kp * 64 + 8 * w];
            ulonglong2 t0 = tp[0], t1 = tp[1], t2 = tp[2], t3 = tp[3];
            acc[0][0] = fma2(wa.x, t0.x, acc[0][0]);
            acc[1][0] = fma2(wa.y, t0.x, acc[1][0]);
            acc[2][0] = fma2(wb.x, t0.x, acc[2][0]);
            acc[3][0] = fma2(wb.y, t0.x, acc[3][0]);
            acc[0][1] = fma2(wa.x, t0.y, acc[0][1]);
            acc[1][1] = fma2(wa.y, t0.y, acc[1][1]);
            acc[2][1] = fma2(wb.x, t0.y, acc[2][1]);
            acc[3][1] = fma2(wb.y, t0.y, acc[3][1]);
            acc[0][2] = fma2(wa.x, t1.x, acc[0][2]);
            acc[1][2] = fma2(wa.y, t1.x, acc[1][2]);
            acc[2][2] = fma2(wb.x, t1.x, acc[2][2]);
            acc[3][2] = fma2(wb.y, t1.x, acc[3][2]);
            acc[0][3] = fma2(wa.x, t1.y, acc[0][3]);
            acc[1][3] = fma2(wa.y, t1.y, acc[1][3]);
            acc[2][3] = fma2(wb.x, t1.y, acc[2][3]);
            acc[3][3] = fma2(wb.y, t1.y, acc[3][3]);
            acc[0][4] = fma2(wa.x, t2.x, acc[0][4]);
            acc[1][4] = fma2(wa.y, t2.x, acc[1][4]);
            acc[2][4] = fma2(wb.x, t2.x, acc[2][4]);
            acc[3][4] = fma2(wb.y, t2.x, acc[3][4]);
            acc[0][5] = fma2(wa.x, t2.y, acc[0][5]);
            acc[1][5] = fma2(wa.y, t2.y, acc[1][5]);
            acc[2][5] = fma2(wb.x, t2.y, acc[2][5]);
            acc[3][5] = fma2(wb.y, t2.y, acc[3][5]);
            acc[0][6] = fma2(wa.x, t3.x, acc[0][6]);
            acc[1][6] = fma2(wa.y, t3.x, acc[1][6]);
            acc[2][6] = fma2(wb.x, t3.x, acc[2][6]);
            acc[3][6] = fma2(wb.y, t3.x, acc[3][6]);
            acc[0][7] = fma2(wa.x, t3.y, acc[0][7]);
            acc[1][7] = fma2(wa.y, t3.y, acc[1][7]);
            acc[2][7] = fma2(wb.x, t3.y, acc[2][7]);
            acc[3][7] = fma2(wb.y, t3.y, acc[3][7]);
        }

        // epilogue: collapse k-halves, +bias, expmap0, store
#pragma unroll
        for (int p = 0; p < 8; p++) {
            float h0 = sum2(acc[0][p]) + bv.x;
            float h1 = sum2(acc[1][p]) + bv.y;
            float h2 = sum2(acc[2][p]) + bv.z;
            float h3 = sum2(acc[3][p]) + bv.w;
            float ss = h0 * h0 + h1 * h1 + h2 * h2 + h3 * h3;
            ss += __shfl_xor_sync(0xffffffff, ss, 16);
            ss += __shfl_xor_sync(0xffffffff, ss, 8);
            ss += __shfl_xor_sync(0xffffffff, ss, 4);
            ss += __shfl_xor_sync(0xffffffff, ss, 2);
            ss += __shfl_xor_sync(0xffffffff, ss, 1);
            float nn = fmaxf(sqrtf(ss), EPSF);
            float f = tanhf(nn) / nn;
            int node = n0 + 8 * w + p;
            if (node < N_NODES) {
                float4 o = make_float4(f * h0, f * h1, f * h2, f * h3);
                *(float4*)&y[node * DIM + 4 * lane] = o;
            }
        }
        __syncthreads();
    }
}

// ---------------------------------------------------------------------------
// Warp-level CSR row gather with 4-deep MLP.
__device__ __forceinline__ float4 gather_row(const int* __restrict__ esrc,
                                             const float* __restrict__ y,
                                             int s, int e, int lane4) {
    float4 a0 = make_float4(0.f, 0.f, 0.f, 0.f);
    float4 a1 = make_float4(0.f, 0.f, 0.f, 0.f);
    float4 a2 = make_float4(0.f, 0.f, 0.f, 0.f);
    float4 a3 = make_float4(0.f, 0.f, 0.f, 0.f);
    int i = s;
    for (; i + 4 <= e; i += 4) {
        int s0 = __ldg(&esrc[i + 0]);
        int s1 = __ldg(&esrc[i + 1]);
        int s2 = __ldg(&esrc[i + 2]);
        int s3 = __ldg(&esrc[i + 3]);
        float4 v0 = __ldg((const float4*)&y[s0 * DIM + lane4]);
        float4 v1 = __ldg((const float4*)&y[s1 * DIM + lane4]);
        float4 v2 = __ldg((const float4*)&y[s2 * DIM + lane4]);
        float4 v3 = __ldg((const float4*)&y[s3 * DIM + lane4]);
        a0.x += v0.x; a0.y += v0.y; a0.z += v0.z; a0.w += v0.w;
        a1.x += v1.x; a1.y += v1.y; a1.z += v1.z; a1.w += v1.w;
        a2.x += v2.x; a2.y += v2.y; a2.z += v2.z; a2.w += v2.w;
        a3.x += v3.x; a3.y += v3.y; a3.z += v3.z; a3.w += v3.w;
    }
    if (i + 2 <= e) {
        int s0 = __ldg(&esrc[i + 0]);
        int s1 = __ldg(&esrc[i + 1]);
        float4 v0 = __ldg((const float4*)&y[s0 * DIM + lane4]);
        float4 v1 = __ldg((const float4*)&y[s1 * DIM + lane4]);
        a0.x += v0.x; a0.y += v0.y; a0.z += v0.z; a0.w += v0.w;
        a1.x += v1.x; a1.y += v1.y; a1.z += v1.z; a1.w += v1.w;
        i += 2;
    }
    if (i < e) {
        int s0 = __ldg(&esrc[i]);
        float4 v0 = __ldg((const float4*)&y[s0 * DIM + lane4]);
        a0.x += v0.x; a0.y += v0.y; a0.z += v0.z; a0.w += v0.w;
    }
    float4 r;
    r.x = (a0.x + a1.x) + (a2.x + a3.x);
    r.y = (a0.y + a1.y) + (a2.y + a3.y);
    r.z = (a0.z + a1.z) + (a2.z + a3.z);
    r.w = (a0.w + a1.w) + (a2.w + a3.w);
    return r;
}

// Layer-1 aggregation fused with relu + logmap0 scaling.
__global__ void __launch_bounds__(256)
gather_kernel(const int* __restrict__ esrc, const int* __restrict__ rs,
              const float* __restrict__ y, float* __restrict__ agg) {
    const int lane = threadIdx.x & 31;
    const int wid  = threadIdx.x >> 5;
    const int node = blockIdx.x * (blockDim.x >> 5) + wid;
    if (node >= N_NODES) return;
    const int s = rs[node];
    const int e = rs[node + 1];
    float4 r = gather_row(esrc, y, s, e, lane * 4);

    r.x = fmaxf(r.x, 0.f); r.y = fmaxf(r.y, 0.f);
    r.z = fmaxf(r.z, 0.f); r.w = fmaxf(r.w, 0.f);

    float ss = r.x * r.x + r.y * r.y + r.z * r.z + r.w * r.w;
    ss += __shfl_xor_sync(0xffffffff, ss, 16);
    ss += __shfl_xor_sync(0xffffffff, ss, 8);
    ss += __shfl_xor_sync(0xffffffff, ss, 4);
    ss += __shfl_xor_sync(0xffffffff, ss, 2);
    ss += __shfl_xor_sync(0xffffffff, ss, 1);
    float n = fmaxf(sqrtf(ss), EPSF);
    float f = atanhf(fminf(n, MAX_NORM)) / n;

    float4 o = make_float4(f * r.x, f * r.y, f * r.z, f * r.w);
    *(float4*)&agg[node * DIM + lane * 4] = o;
}

// Layer-2 aggregation fused with classifier.
__global__ void __launch_bounds__(256)
gather_cls_kernel(const int* __restrict__ esrc, const int* __restrict__ rs,
                  const float* __restrict__ y, const float* __restrict__ Wc,
                  const float* __restrict__ bc, float* __restrict__ out) {
    __shared__ float Wcs[NUM_CLASSES * DIM];
    __shared__ float bcs[NUM_CLASSES];
    const int tid = threadIdx.x;
    for (int i = tid; i < NUM_CLASSES * DIM; i += blockDim.x) Wcs[i] = Wc[i];
    if (tid < NUM_CLASSES) bcs[tid] = bc[tid];
    __syncthreads();

    const int lane = tid & 31;
    const int wid  = tid >> 5;
    const int node = blockIdx.x * (blockDim.x >> 5) + wid;
    if (node >= N_NODES) return;

    const int s = rs[node];
    const int e = rs[node + 1];
    float4 h = gather_row(esrc, y, s, e, lane * 4);

    h.x = fmaxf(h.x, 0.f); h.y = fmaxf(h.y, 0.f);
    h.z = fmaxf(h.z, 0.f); h.w = fmaxf(h.w, 0.f);

    float sq = h.x * h.x + h.y * h.y + h.z * h.z + h.w * h.w;
    sq += __shfl_xor_sync(0xffffffff, sq, 16);
    sq += __shfl_xor_sync(0xffffffff, sq, 8);
    sq += __shfl_xor_sync(0xffffffff, sq, 4);
    sq += __shfl_xor_sync(0xffffffff, sq, 2);
    sq += __shfl_xor_sync(0xffffffff, sq, 1);
    float n = fmaxf(sqrtf(sq), EPSF);
    float f = atanhf(fminf(n, MAX_NORM)) / n;
    float4 t = make_float4(f * h.x, f * h.y, f * h.z, f * h.w);

#pragma unroll
    for (int c = 0; c < NUM_CLASSES; c++) {
        float4 w = *(const float4*)&Wcs[c * DIM + lane * 4];
        float p = t.x * w.x + t.y * w.y + t.z * w.z + t.w * w.w;
        p += __shfl_xor_sync(0xffffffff, p, 16);
        p += __shfl_xor_sync(0xffffffff, p, 8);
        p += __shfl_xor_sync(0xffffffff, p, 4);
        p += __shfl_xor_sync(0xffffffff, p, 2);
        p += __shfl_xor_sync(0xffffffff, p, 1);
        if (lane == 0) out[node * NUM_CLASSES + c] = p + bcs[c];
    }
}

// ---------------------------------------------------------------------------
extern "C" void kernel_launch(void* const* d_in, const int* in_sizes, int n_in,
                              void* d_out, int out_size) {
    const int*   e32 = (const int*)d_in[0];
    const float* x   = (const float*)d_in[1];
    const float* W1  = (const float*)d_in[2];
    const float* b1  = (const float*)d_in[3];
    const float* W2  = (const float*)d_in[4];
    const float* b2  = (const float*)d_in[5];
    const float* Wc  = (const float*)d_in[6];
    const float* bc  = (const float*)d_in[7];
    float* out = (float*)d_out;

    float *y, *agg;
    u64 *xTp, *Wp1, *Wp2;
    int *rs, *es;
    cudaGetSymbolAddress((void**)&y,   g_y);
    cudaGetSymbolAddress((void**)&agg, g_agg);
    cudaGetSymbolAddress((void**)&xTp, g_xTp);
    cudaGetSymbolAddress((void**)&Wp1, g_Wp1);
    cudaGetSymbolAddress((void**)&Wp2, g_Wp2);
    cudaGetSymbolAddress((void**)&rs,  g_rowstart);
    cudaGetSymbolAddress((void**)&es,  g_esrc);

    // one-time host resources (no device memory involved)
    static cudaStream_t s2 = nullptr;
    static cudaEvent_t evF = nullptr, evW = nullptr, evC = nullptr;
    static bool attr_done = false;
    if (!attr_done) {
        attr_done = true;
        cudaStreamCreateWithFlags(&s2, cudaStreamNonBlocking);
        cudaEventCreateWithFlags(&evF, cudaEventDisableTiming);
        cudaEventCreateWithFlags(&evW, cudaEventDisableTiming);
        cudaEventCreateWithFlags(&evC, cudaEventDisableTiming);
        cudaFuncSetAttribute(mm_kernel,
                             cudaFuncAttributeMaxDynamicSharedMemorySize, MM_SMEM);
    }

    const int ftblocks = (N_NODES + 31) / 32;   // 1563
    const int gblocks  = (N_NODES + 7) / 8;

    // fork side stream: W prep + CSR build overlap layer-1 transform
    cudaEventRecord(evF, 0);
    cudaStreamWaitEvent(s2, evF, 0);
    wprep_kernel<<<8, 256, 0, s2>>>(W1, W2, Wp1, Wp2);
    cudaEventRecord(evW, s2);
    csr_kernel<<<CSR_BLOCKS, CSR_THREADS, 0, s2>>>(e32);
    cudaEventRecord(evC, s2);

    // main stream
    facT_kernel<<<ftblocks, 256>>>(x, xTp, 1);
    cudaStreamWaitEvent(0, evW, 0);                    // mm1 needs Wp1
    mm_kernel<<<MM_GRID, 256, MM_SMEM>>>(xTp, Wp1, b1, y);
    cudaStreamWaitEvent(0, evC, 0);                    // gather needs CSR
    gather_kernel<<<gblocks, 256>>>(es, rs, y, agg);   // + relu + logmap0
    facT_kernel<<<ftblocks, 256>>>(agg, xTp, 0);       // pure transpose
    mm_kernel<<<MM_GRID, 256, MM_SMEM>>>(xTp, Wp2, b2, y);
    gather_cls_kernel<<<gblocks, 256>>>(es, rs, y, Wc, bc, out);
}

// round 9
// speedup vs baseline: 1.2574x; 1.0290x over previous
#include <cuda_runtime.h>
#include <cuda_bf16.h>
#include <math.h>

#define N_NODES 50000
#define N_EDGES 600000
#define DIM 128
#define NUM_CLASSES 10
#define EPSF 1e-15f
#define MAX_NORM (1.0f - 1e-5f)

#define KP 64                      // k-pairs
#define XTP 50048                  // node pitch for pair-packed xT (64*782)
#define FT_PITCH 129
#define MM_TILES ((N_NODES + 63) / 64)   // 782
#define MM_GRID 296
#define MM_SMEM ((KP * DIM + KP * 64) * 8)   // Wsh 64KB + Tsh 32KB = 96KB

#define CSR_BLOCKS 49
#define CSR_THREADS 1024

typedef unsigned long long u64;

// scratch (device globals: no allocation allowed)
__device__ float g_y[N_NODES * DIM];
__device__ float g_agg[N_NODES * DIM];
__device__ u64   g_xTp[KP * XTP];        // (t[2kp][n], t[2kp+1][n])
__device__ u64   g_Wp1[KP * DIM];        // (W[j][2kp], W[j][2kp+1]) at [kp*128+j]
__device__ u64   g_Wp2[KP * DIM];
__device__ int   g_mult;
__device__ int   g_count[N_NODES];
__device__ int   g_cursor[N_NODES];
__device__ int   g_rowstart[N_NODES + 1];
__device__ int   g_bsum[CSR_BLOCKS];
__device__ volatile unsigned g_bar_gen;   // monotonic across graph replays
__device__ unsigned g_bar_cnt;            // self-resets
__device__ int   g_esrc[N_EDGES];

// ---------------------------------------------------------------------------
// packed fp32x2 helpers (Blackwell FFMA2 — PTX-only)
__device__ __forceinline__ u64 fma2(u64 a, u64 b, u64 c) {
    u64 d;
    asm("fma.rn.f32x2 %0, %1, %2, %3;" : "=l"(d) : "l"(a), "l"(b), "l"(c));
    return d;
}
__device__ __forceinline__ u64 pack2(float lo, float hi) {
    u64 r;
    asm("mov.b64 %0, {%1, %2};" : "=l"(r) : "f"(lo), "f"(hi));
    return r;
}
__device__ __forceinline__ void unpack2(u64 v, float& lo, float& hi) {
    asm("mov.b64 {%0, %1}, %2;" : "=f"(lo), "=f"(hi) : "l"(v));
}
__device__ __forceinline__ float sum2(u64 v) {
    float lo, hi;
    unpack2(v, lo, hi);
    return lo + hi;
}

// ---------------------------------------------------------------------------
// software grid barrier (all CSR_BLOCKS resident: 49 << 148 SMs)
__device__ __forceinline__ void grid_barrier() {
    __syncthreads();
    if (threadIdx.x == 0) {
        __threadfence();
        unsigned my = g_bar_gen;
        unsigned a = atomicAdd(&g_bar_cnt, 1);
        if (a == CSR_BLOCKS - 1) {
            g_bar_cnt = 0;
            __threadfence();
            g_bar_gen = my + 1;
        } else {
            while (g_bar_gen == my) __nanosleep(32);
        }
    }
    __syncthreads();
}

// ---------------------------------------------------------------------------
// Fused CSR build (side stream): detect + zero + hist + scan + bucket scatter.
__global__ void __launch_bounds__(CSR_THREADS)
csr_kernel(const int* __restrict__ e32) {
    const int b = blockIdx.x, t = threadIdx.x;
    const int gid = b * CSR_THREADS + t;
    const int nth = CSR_BLOCKS * CSR_THREADS;

    if (b == 0 && t < 32) {
        int v1 = e32[2 * t + 1];
        int bad = __any_sync(0xffffffffu, v1 != 0);
        if (t == 0) g_mult = bad ? 1 : 2;
    }
    if (gid < N_NODES) g_count[gid] = 0;
    grid_barrier();

    const int m = g_mult;
    for (int e = gid; e < N_EDGES; e += nth) {
        int dst = e32[(long long)(N_EDGES + e) * m];
        atomicAdd(&g_count[dst], 1);
    }
    grid_barrier();

    __shared__ int wsum[32];
    __shared__ int part[2];
    const int lane = t & 31, w = t >> 5;
    int v = (gid < N_NODES) ? g_count[gid] : 0;
    int x = v;
#pragma unroll
    for (int d = 1; d < 32; d <<= 1) {
        int y = __shfl_up_sync(0xffffffffu, x, d);
        if (lane >= d) x += y;
    }
    if (lane == 31) wsum[w] = x;
    __syncthreads();
    if (w == 0) {
        int s = wsum[lane];
#pragma unroll
        for (int d = 1; d < 32; d <<= 1) {
            int y = __shfl_up_sync(0xffffffffu, s, d);
            if (lane >= d) s += y;
        }
        wsum[lane] = s;
    }
    __syncthreads();
    int excl = x - v + (w ? wsum[w - 1] : 0);
    if (t == CSR_THREADS - 1) g_bsum[b] = excl + v;
    grid_barrier();

    if (t < 64) {
        int pv = (t < b) ? g_bsum[t] : 0;
#pragma unroll
        for (int d = 16; d > 0; d >>= 1)
            pv += __shfl_xor_sync(0xffffffffu, pv, d);
        if (lane == 0) part[w] = pv;
    }
    __syncthreads();
    const int boff = part[0] + part[1];
    if (gid < N_NODES) {
        int rv = excl + boff;
        g_rowstart[gid] = rv;
        g_cursor[gid] = rv;
    }
    if (gid == 0) g_rowstart[N_NODES] = N_EDGES;
    grid_barrier();

    for (int e = gid; e < N_EDGES; e += nth) {
        int src = e32[(long long)e * m];
        int dst = e32[(long long)(N_EDGES + e) * m];
        int pos = atomicAdd(&g_cursor[dst], 1);
        g_esrc[pos] = src;
    }
}

// ---------------------------------------------------------------------------
// wprep: transpose W1,W2 into k-pair layout Wp[kp*128 + j] = (W[j][2kp], W[j][2kp+1])
__global__ void __launch_bounds__(256)
wprep_kernel(const float* __restrict__ W1, const float* __restrict__ W2,
             u64* __restrict__ Wp1, u64* __restrict__ Wp2) {
    __shared__ float s[32 * FT_PITCH];
    const int mtx = blockIdx.x >> 2;
    const int j0 = (blockIdx.x & 3) * 32;
    const float* W = mtx ? W2 : W1;
    u64* Wp = mtx ? Wp2 : Wp1;
    const int tid = threadIdx.x;

#pragma unroll
    for (int q = 0; q < 4; q++) {
        int idx = q * 256 + tid;          // 0..1023 float4s
        int jj = idx >> 5, k4 = idx & 31;
        float4 v = __ldg((const float4*)&W[(j0 + jj) * DIM + k4 * 4]);
        float* sr = &s[jj * FT_PITCH + k4 * 4];
        sr[0] = v.x; sr[1] = v.y; sr[2] = v.z; sr[3] = v.w;
    }
    __syncthreads();
#pragma unroll
    for (int q = 0; q < 8; q++) {
        int idx = q * 256 + tid;          // 0..2047
        int kp = idx >> 5, jj = idx & 31;
        Wp[kp * DIM + j0 + jj] =
            pack2(s[jj * FT_PITCH + 2 * kp], s[jj * FT_PITCH + 2 * kp + 1]);
    }
}

// ---------------------------------------------------------------------------
// facT: 32-node tile -> (optional logmap0 factor) -> k-pair transposed write.
__global__ void __launch_bounds__(256)
facT_kernel(const float* __restrict__ in, u64* __restrict__ xTp, int do_norm) {
    __shared__ float s[32 * FT_PITCH];
    __shared__ float facs[32];
    const int tid = threadIdx.x, lane = tid & 31, w = tid >> 5;
    const int node0 = blockIdx.x * 32;

#pragma unroll
    for (int q = 0; q < 4; q++) {
        int idx = q * 256 + tid;
        int n = idx >> 5, c4 = idx & 31;
        float4 v = make_float4(0.f, 0.f, 0.f, 0.f);
        if (node0 + n < N_NODES)
            v = __ldg((const float4*)&in[(node0 + n) * DIM + c4 * 4]);
        float* sr = &s[n * FT_PITCH + c4 * 4];
        sr[0] = v.x; sr[1] = v.y; sr[2] = v.z; sr[3] = v.w;
    }
    __syncthreads();

    if (do_norm) {
#pragma unroll
        for (int j = 0; j < 4; j++) {
            int n = w * 4 + j;
            const float* sr = &s[n * FT_PITCH];
            float a0 = sr[lane], a1 = sr[lane + 32];
            float a2 = sr[lane + 64], a3 = sr[lane + 96];
            float ss = a0 * a0 + a1 * a1 + a2 * a2 + a3 * a3;
            ss += __shfl_xor_sync(0xffffffff, ss, 16);
            ss += __shfl_xor_sync(0xffffffff, ss, 8);
            ss += __shfl_xor_sync(0xffffffff, ss, 4);
            ss += __shfl_xor_sync(0xffffffff, ss, 2);
            ss += __shfl_xor_sync(0xffffffff, ss, 1);
            if (lane == 0) {
                float nn = fmaxf(sqrtf(ss), EPSF);
                facs[n] = atanhf(fminf(nn, MAX_NORM)) / nn;
            }
        }
    } else {
        if (tid < 32) facs[tid] = 1.0f;
    }
    __syncthreads();

    const int n = node0 + lane;
    const bool ok = n < N_NODES;
    const float fl = facs[lane];
#pragma unroll
    for (int i = 0; i < 8; i++) {
        int kp = w + 8 * i;
        float vlo = fl * s[lane * FT_PITCH + 2 * kp];
        float vhi = fl * s[lane * FT_PITCH + 2 * kp + 1];
        if (ok) xTp[kp * XTP + n] = pack2(vlo, vhi);
    }
}

// ---------------------------------------------------------------------------
// mm: y = expmap0( t @ W^T + b ). k-pair packed operands.
// Thread owns cols {lane, lane+32, lane+64, lane+96}: W reads are 4 LDS.64s
// with 8B lane stride = 2 wavefronts each (structural minimum, no conflicts).
__global__ void __launch_bounds__(256, 2)
mm_kernel(const u64* __restrict__ xTp, const u64* __restrict__ Wp,
          const float* __restrict__ bias, float* __restrict__ y) {
    extern __shared__ u64 sm8[];
    u64* Wsh = sm8;                // [kp][j], 64x128
    u64* Tsh = sm8 + KP * DIM;     // [kp][n], 64x64

    const int tid = threadIdx.x, lane = tid & 31, w = tid >> 5;

    {
        const ulonglong2* wg = (const ulonglong2*)Wp;
        ulonglong2* ws = (ulonglong2*)Wsh;
        for (int i = tid; i < KP * DIM / 2; i += 256) ws[i] = wg[i];
    }
    const float b0 = __ldg(&bias[lane]);
    const float b1 = __ldg(&bias[lane + 32]);
    const float b2 = __ldg(&bias[lane + 64]);
    const float b3 = __ldg(&bias[lane + 96]);
    __syncthreads();

    for (int tile = blockIdx.x; tile < MM_TILES; tile += gridDim.x) {
        const int n0 = tile * 64;

        // stage Tsh (coalesced ulonglong2 copies)
#pragma unroll
        for (int q = 0; q < 8; q++) {
            int idx = q * 256 + tid;            // 0..2047 ulonglong2
            int kp = idx >> 5, c2 = idx & 31;
            *(ulonglong2*)&Tsh[kp * 64 + c2 * 2] =
                *(const ulonglong2*)&xTp[kp * XTP + n0 + c2 * 2];
        }
        __syncthreads();

        u64 acc[4][8];
#pragma unroll
        for (int c = 0; c < 4; c++)
#pragma unroll
            for (int p = 0; p < 8; p++) acc[c][p] = 0ULL;

#pragma unroll 2
        for (int kp = 0; kp < KP; kp++) {
            const u64* wrow = &Wsh[kp * DIM + lane];
            u64 w0 = wrow[0];
            u64 w1 = wrow[32];
            u64 w2 = wrow[64];
            u64 w3 = wrow[96];
            const ulonglong2* tp = (const ulonglong2*)&Tsh[kp * 64 + 8 * w];
            ulonglong2 t0 = tp[0], t1 = tp[1], t2 = tp[2], t3 = tp[3];
            acc[0][0] = fma2(w0, t0.x, acc[0][0]);
            acc[1][0] = fma2(w1, t0.x, acc[1][0]);
            acc[2][0] = fma2(w2, t0.x, acc[2][0]);
            acc[3][0] = fma2(w3, t0.x, acc[3][0]);
            acc[0][1] = fma2(w0, t0.y, acc[0][1]);
            acc[1][1] = fma2(w1, t0.y, acc[1][1]);
            acc[2][1] = fma2(w2, t0.y, acc[2][1]);
            acc[3][1] = fma2(w3, t0.y, acc[3][1]);
            acc[0][2] = fma2(w0, t1.x, acc[0][2]);
            acc[1][2] = fma2(w1, t1.x, acc[1][2]);
            acc[2][2] = fma2(w2, t1.x, acc[2][2]);
            acc[3][2] = fma2(w3, t1.x, acc[3][2]);
            acc[0][3] = fma2(w0, t1.y, acc[0][3]);
            acc[1][3] = fma2(w1, t1.y, acc[1][3]);
            acc[2][3] = fma2(w2, t1.y, acc[2][3]);
            acc[3][3] = fma2(w3, t1.y, acc[3][3]);
            acc[0][4] = fma2(w0, t2.x, acc[0][4]);
            acc[1][4] = fma2(w1, t2.x, acc[1][4]);
            acc[2][4] = fma2(w2, t2.x, acc[2][4]);
            acc[3][4] = fma2(w3, t2.x, acc[3][4]);
            acc[0][5] = fma2(w0, t2.y, acc[0][5]);
            acc[1][5] = fma2(w1, t2.y, acc[1][5]);
            acc[2][5] = fma2(w2, t2.y, acc[2][5]);
            acc[3][5] = fma2(w3, t2.y, acc[3][5]);
            acc[0][6] = fma2(w0, t3.x, acc[0][6]);
            acc[1][6] = fma2(w1, t3.x, acc[1][6]);
            acc[2][6] = fma2(w2, t3.x, acc[2][6]);
            acc[3][6] = fma2(w3, t3.x, acc[3][6]);
            acc[0][7] = fma2(w0, t3.y, acc[0][7]);
            acc[1][7] = fma2(w1, t3.y, acc[1][7]);
            acc[2][7] = fma2(w2, t3.y, acc[2][7]);
            acc[3][7] = fma2(w3, t3.y, acc[3][7]);
        }

        // epilogue: collapse k-halves, +bias, expmap0, store (4 coalesced STG.32)
#pragma unroll
        for (int p = 0; p < 8; p++) {
            float h0 = sum2(acc[0][p]) + b0;
            float h1 = sum2(acc[1][p]) + b1;
            float h2 = sum2(acc[2][p]) + b2;
            float h3 = sum2(acc[3][p]) + b3;
            float ss = h0 * h0 + h1 * h1 + h2 * h2 + h3 * h3;
            ss += __shfl_xor_sync(0xffffffff, ss, 16);
            ss += __shfl_xor_sync(0xffffffff, ss, 8);
            ss += __shfl_xor_sync(0xffffffff, ss, 4);
            ss += __shfl_xor_sync(0xffffffff, ss, 2);
            ss += __shfl_xor_sync(0xffffffff, ss, 1);
            float nn = fmaxf(sqrtf(ss), EPSF);
            float f = tanhf(nn) / nn;
            int node = n0 + 8 * w + p;
            if (node < N_NODES) {
                float* yr = &y[node * DIM + lane];
                yr[0]  = f * h0;
                yr[32] = f * h1;
                yr[64] = f * h2;
                yr[96] = f * h3;
            }
        }
        __syncthreads();
    }
}

// ---------------------------------------------------------------------------
// Warp-level CSR row gather with 4-deep MLP.
__device__ __forceinline__ float4 gather_row(const int* __restrict__ esrc,
                                             const float* __restrict__ y,
                                             int s, int e, int lane4) {
    float4 a0 = make_float4(0.f, 0.f, 0.f, 0.f);
    float4 a1 = make_float4(0.f, 0.f, 0.f, 0.f);
    float4 a2 = make_float4(0.f, 0.f, 0.f, 0.f);
    float4 a3 = make_float4(0.f, 0.f, 0.f, 0.f);
    int i = s;
    for (; i + 4 <= e; i += 4) {
        int s0 = __ldg(&esrc[i + 0]);
        int s1 = __ldg(&esrc[i + 1]);
        int s2 = __ldg(&esrc[i + 2]);
        int s3 = __ldg(&esrc[i + 3]);
        float4 v0 = __ldg((const float4*)&y[s0 * DIM + lane4]);
        float4 v1 = __ldg((const float4*)&y[s1 * DIM + lane4]);
        float4 v2 = __ldg((const float4*)&y[s2 * DIM + lane4]);
        float4 v3 = __ldg((const float4*)&y[s3 * DIM + lane4]);
        a0.x += v0.x; a0.y += v0.y; a0.z += v0.z; a0.w += v0.w;
        a1.x += v1.x; a1.y += v1.y; a1.z += v1.z; a1.w += v1.w;
        a2.x += v2.x; a2.y += v2.y; a2.z += v2.z; a2.w += v2.w;
        a3.x += v3.x; a3.y += v3.y; a3.z += v3.z; a3.w += v3.w;
    }
    if (i + 2 <= e) {
        int s0 = __ldg(&esrc[i + 0]);
        int s1 = __ldg(&esrc[i + 1]);
        float4 v0 = __ldg((const float4*)&y[s0 * DIM + lane4]);
        float4 v1 = __ldg((const float4*)&y[s1 * DIM + lane4]);
        a0.x += v0.x; a0.y += v0.y; a0.z += v0.z; a0.w += v0.w;
        a1.x += v1.x; a1.y += v1.y; a1.z += v1.z; a1.w += v1.w;
        i += 2;
    }
    if (i < e) {
        int s0 = __ldg(&esrc[i]);
        float4 v0 = __ldg((const float4*)&y[s0 * DIM + lane4]);
        a0.x += v0.x; a0.y += v0.y; a0.z += v0.z; a0.w += v0.w;
    }
    float4 r;
    r.x = (a0.x + a1.x) + (a2.x + a3.x);
    r.y = (a0.y + a1.y) + (a2.y + a3.y);
    r.z = (a0.z + a1.z) + (a2.z + a3.z);
    r.w = (a0.w + a1.w) + (a2.w + a3.w);
    return r;
}

// Layer-1 aggregation fused with relu + logmap0 scaling.
__global__ void __launch_bounds__(256)
gather_kernel(const int* __restrict__ esrc, const int* __restrict__ rs,
              const float* __restrict__ y, float* __restrict__ agg) {
    const int lane = threadIdx.x & 31;
    const int wid  = threadIdx.x >> 5;
    const int node = blockIdx.x * (blockDim.x >> 5) + wid;
    if (node >= N_NODES) return;
    const int s = rs[node];
    const int e = rs[node + 1];
    float4 r = gather_row(esrc, y, s, e, lane * 4);

    r.x = fmaxf(r.x, 0.f); r.y = fmaxf(r.y, 0.f);
    r.z = fmaxf(r.z, 0.f); r.w = fmaxf(r.w, 0.f);

    float ss = r.x * r.x + r.y * r.y + r.z * r.z + r.w * r.w;
    ss += __shfl_xor_sync(0xffffffff, ss, 16);
    ss += __shfl_xor_sync(0xffffffff, ss, 8);
    ss += __shfl_xor_sync(0xffffffff, ss, 4);
    ss += __shfl_xor_sync(0xffffffff, ss, 2);
    ss += __shfl_xor_sync(0xffffffff, ss, 1);
    float n = fmaxf(sqrtf(ss), EPSF);
    float f = atanhf(fminf(n, MAX_NORM)) / n;

    float4 o = make_float4(f * r.x, f * r.y, f * r.z, f * r.w);
    *(float4*)&agg[node * DIM + lane * 4] = o;
}

// Layer-2 aggregation fused with classifier.
__global__ void __launch_bounds__(256)
gather_cls_kernel(const int* __restrict__ esrc, const int* __restrict__ rs,
                  const float* __restrict__ y, const float* __restrict__ Wc,
                  const float* __restrict__ bc, float* __restrict__ out) {
    __shared__ float Wcs[NUM_CLASSES * DIM];
    __shared__ float bcs[NUM_CLASSES];
    const int tid = threadIdx.x;
    for (int i = tid; i < NUM_CLASSES * DIM; i += blockDim.x) Wcs[i] = Wc[i];
    if (tid < NUM_CLASSES) bcs[tid] = bc[tid];
    __syncthreads();

    const int lane = tid & 31;
    const int wid  = tid >> 5;
    const int node = blockIdx.x * (blockDim.x >> 5) + wid;
    if (node >= N_NODES) return;

    const int s = rs[node];
    const int e = rs[node + 1];
    float4 h = gather_row(esrc, y, s, e, lane * 4);

    h.x = fmaxf(h.x, 0.f); h.y = fmaxf(h.y, 0.f);
    h.z = fmaxf(h.z, 0.f); h.w = fmaxf(h.w, 0.f);

    float sq = h.x * h.x + h.y * h.y + h.z * h.z + h.w * h.w;
    sq += __shfl_xor_sync(0xffffffff, sq, 16);
    sq += __shfl_xor_sync(0xffffffff, sq, 8);
    sq += __shfl_xor_sync(0xffffffff, sq, 4);
    sq += __shfl_xor_sync(0xffffffff, sq, 2);
    sq += __shfl_xor_sync(0xffffffff, sq, 1);
    float n = fmaxf(sqrtf(sq), EPSF);
    float f = atanhf(fminf(n, MAX_NORM)) / n;
    float4 t = make_float4(f * h.x, f * h.y, f * h.z, f * h.w);

#pragma unroll
    for (int c = 0; c < NUM_CLASSES; c++) {
        float4 w = *(const float4*)&Wcs[c * DIM + lane * 4];
        float p = t.x * w.x + t.y * w.y + t.z * w.z + t.w * w.w;
        p += __shfl_xor_sync(0xffffffff, p, 16);
        p += __shfl_xor_sync(0xffffffff, p, 8);
        p += __shfl_xor_sync(0xffffffff, p, 4);
        p += __shfl_xor_sync(0xffffffff, p, 2);
        p += __shfl_xor_sync(0xffffffff, p, 1);
        if (lane == 0) out[node * NUM_CLASSES + c] = p + bcs[c];
    }
}

// ---------------------------------------------------------------------------
extern "C" void kernel_launch(void* const* d_in, const int* in_sizes, int n_in,
                              void* d_out, int out_size) {
    const int*   e32 = (const int*)d_in[0];
    const float* x   = (const float*)d_in[1];
    const float* W1  = (const float*)d_in[2];
    const float* b1  = (const float*)d_in[3];
    const float* W2  = (const float*)d_in[4];
    const float* b2  = (const float*)d_in[5];
    const float* Wc  = (const float*)d_in[6];
    const float* bc  = (const float*)d_in[7];
    float* out = (float*)d_out;

    float *y, *agg;
    u64 *xTp, *Wp1, *Wp2;
    int *rs, *es;
    cudaGetSymbolAddress((void**)&y,   g_y);
    cudaGetSymbolAddress((void**)&agg, g_agg);
    cudaGetSymbolAddress((void**)&xTp, g_xTp);
    cudaGetSymbolAddress((void**)&Wp1, g_Wp1);
    cudaGetSymbolAddress((void**)&Wp2, g_Wp2);
    cudaGetSymbolAddress((void**)&rs,  g_rowstart);
    cudaGetSymbolAddress((void**)&es,  g_esrc);

    // one-time host resources (no device memory involved)
    static cudaStream_t s2 = nullptr;
    static cudaEvent_t evF = nullptr, evW = nullptr, evC = nullptr;
    static bool attr_done = false;
    if (!attr_done) {
        attr_done = true;
        cudaStreamCreateWithFlags(&s2, cudaStreamNonBlocking);
        cudaEventCreateWithFlags(&evF, cudaEventDisableTiming);
        cudaEventCreateWithFlags(&evW, cudaEventDisableTiming);
        cudaEventCreateWithFlags(&evC, cudaEventDisableTiming);
        cudaFuncSetAttribute(mm_kernel,
                             cudaFuncAttributeMaxDynamicSharedMemorySize, MM_SMEM);
    }

    const int ftblocks = (N_NODES + 31) / 32;   // 1563
    const int gblocks  = (N_NODES + 7) / 8;

    // fork side stream: W prep + CSR build overlap layer-1 transform
    cudaEventRecord(evF, 0);
    cudaStreamWaitEvent(s2, evF, 0);
    wprep_kernel<<<8, 256, 0, s2>>>(W1, W2, Wp1, Wp2);
    cudaEventRecord(evW, s2);
    csr_kernel<<<CSR_BLOCKS, CSR_THREADS, 0, s2>>>(e32);
    cudaEventRecord(evC, s2);

    // main stream
    facT_kernel<<<ftblocks, 256>>>(x, xTp, 1);
    cudaStreamWaitEvent(0, evW, 0);                    // mm1 needs Wp1
    mm_kernel<<<MM_GRID, 256, MM_SMEM>>>(xTp, Wp1, b1, y);
    cudaStreamWaitEvent(0, evC, 0);                    // gather needs CSR
    gather_kernel<<<gblocks, 256>>>(es, rs, y, agg);   // + relu + logmap0
    facT_kernel<<<ftblocks, 256>>>(agg, xTp, 0);       // pure transpose
    mm_kernel<<<MM_GRID, 256, MM_SMEM>>>(xTp, Wp2, b2, y);
    gather_cls_kernel<<<gblocks, 256>>>(es, rs, y, Wc, bc, out);
}